// round 13
// baseline (speedup 1.0000x reference)
#include <cuda_runtime.h>
#include <cuda_bf16.h>
#include <math.h>

// ---------------- problem constants ----------------
#define CB 8       // batch
#define CT 128     // time
#define CE 512     // embed dim
#define CH 1024    // hidden
#define CM 512     // mem hidden
#define CM2 1024   // 2*M
#define CS 16
#define CU 128
#define CW 1024
#define CV 32000
#define C3H 3072
#define CF 2048    // H + 2M

// ---------------- fp32 scratch ----------------
__device__ float g_gi[CB * CT * C3H];
__device__ float g_rnn[CB * CT * CH];
__device__ float g_proj_s[CB * CS * CH];
__device__ float g_proj_u[CB * CU * CH];
__device__ float g_sc_s[CB * CT * CS];
__device__ float g_sc_u[CB * CT * CU];
__device__ float g_sc_w[CB * CT * CW];
__device__ unsigned g_bar_arr = 0;
__device__ volatile unsigned g_bar_gen = 0;

// ---------------- bf16 scratch ----------------
__device__ __nv_bfloat16 gb_emb[CB * CT * CE];
__device__ __nv_bfloat16 gb_h1[CB * CT * CH];
__device__ __nv_bfloat16 gb_feat[CB * CT * CF];
__device__ __nv_bfloat16 gb_suw[CB * CT * CW];
__device__ __nv_bfloat16 gb_sout[CB * CS * CM];
__device__ __nv_bfloat16 gb_uout[CB * CU * CM];
__device__ __nv_bfloat16 gb_wout[CB * CW * CM2];
__device__ __nv_bfloat16 gb_wT[CB * CM2 * CW];
__device__ __nv_bfloat16 gb_pw[CB * CW * CH];
__device__ __nv_bfloat16 gb_Wih0[C3H * CE];
__device__ __nv_bfloat16 gb_Wih1[C3H * CH];
__device__ __nv_bfloat16 gb_atts[CH * CM];
__device__ __nv_bfloat16 gb_attu[CH * CM];
__device__ __nv_bfloat16 gb_attw[CH * CM2];
__device__ __nv_bfloat16 gb_outw[(size_t)CV * CF];   // 131 MB
__device__ __nv_bfloat16 g_hbf[2][CB * CH];          // GRU h broadcast (double buffer)

// ---------------- grid barrier (LDG-poll, no atomic polling) ----------------
// Waiters poll a volatile global with plain L2 loads: same-address L2 atomics
// serialize at ~32cyc/op (32 pollers -> ~1000cyc/round), plain LDG does not.
__device__ __forceinline__ void grid_sync_all(unsigned nb) {
    __syncthreads();
    if (threadIdx.x == 0) {
        __threadfence();
        unsigned gen = g_bar_gen;
        if (atomicAdd(&g_bar_arr, 1u) == nb - 1u) {
            atomicExch(&g_bar_arr, 0u);
            __threadfence();
            g_bar_gen = gen + 1u;
        } else {
            while (g_bar_gen == gen) { }
            __threadfence();
        }
    }
    __syncthreads();
}

// ---------------- block reductions (256 threads) ----------------
__device__ __forceinline__ float blockReduceMax256(float v, float* red) {
    #pragma unroll
    for (int o = 16; o; o >>= 1) v = fmaxf(v, __shfl_xor_sync(0xffffffffu, v, o));
    if ((threadIdx.x & 31) == 0) red[threadIdx.x >> 5] = v;
    __syncthreads();
    if (threadIdx.x < 32) {
        float r = (threadIdx.x < 8) ? red[threadIdx.x] : -INFINITY;
        #pragma unroll
        for (int o = 4; o; o >>= 1) r = fmaxf(r, __shfl_xor_sync(0xffffffffu, r, o));
        if (threadIdx.x == 0) red[0] = r;
    }
    __syncthreads();
    float out = red[0];
    __syncthreads();
    return out;
}

__device__ __forceinline__ float blockReduceSum256(float v, float* red) {
    #pragma unroll
    for (int o = 16; o; o >>= 1) v += __shfl_xor_sync(0xffffffffu, v, o);
    if ((threadIdx.x & 31) == 0) red[threadIdx.x >> 5] = v;
    __syncthreads();
    if (threadIdx.x < 32) {
        float r = (threadIdx.x < 8) ? red[threadIdx.x] : 0.f;
        #pragma unroll
        for (int o = 4; o; o >>= 1) r += __shfl_xor_sync(0xffffffffu, r, o);
        if (threadIdx.x == 0) red[0] = r;
    }
    __syncthreads();
    float out = red[0];
    __syncthreads();
    return out;
}

// ---------------- single merged fp32->bf16 convert (9 segments) ----------------
#define SEG0 (C3H * CE / 4)
#define SEG1 (SEG0 + C3H * CH / 4)
#define SEG2 (SEG1 + CH * CM / 4)
#define SEG3 (SEG2 + CH * CM / 4)
#define SEG4 (SEG3 + CH * CM2 / 4)
#define SEG5 (SEG4 + (size_t)CV * CF / 4)
#define SEG6 (SEG5 + CB * CS * CM / 4)
#define SEG7 (SEG6 + CB * CU * CM / 4)
#define SEG8 (SEG7 + CB * CW * CM2 / 4)

__global__ void convert_all_kernel(
    const float* __restrict__ s0, const float* __restrict__ s1,
    const float* __restrict__ s2, const float* __restrict__ s3,
    const float* __restrict__ s4, const float* __restrict__ s5,
    const float* __restrict__ s6, const float* __restrict__ s7,
    const float* __restrict__ s8)
{
    size_t i4 = (size_t)blockIdx.x * 256 + threadIdx.x;
    const float* src; __nv_bfloat16* dst; size_t off;
    if      (i4 < SEG0) { src = s0; dst = gb_Wih0; off = i4; }
    else if (i4 < SEG1) { src = s1; dst = gb_Wih1; off = i4 - SEG0; }
    else if (i4 < SEG2) { src = s2; dst = gb_atts; off = i4 - SEG1; }
    else if (i4 < SEG3) { src = s3; dst = gb_attu; off = i4 - SEG2; }
    else if (i4 < SEG4) { src = s4; dst = gb_attw; off = i4 - SEG3; }
    else if (i4 < SEG5) { src = s5; dst = gb_outw; off = i4 - SEG4; }
    else if (i4 < SEG6) { src = s6; dst = gb_sout; off = i4 - SEG5; }
    else if (i4 < SEG7) { src = s7; dst = gb_uout; off = i4 - SEG6; }
    else if (i4 < SEG8) { src = s8; dst = gb_wout; off = i4 - SEG7; }
    else return;
    float4 v = ((const float4*)src)[off];
    __nv_bfloat162* d = (__nv_bfloat162*)(dst + off * 4);
    d[0] = __floats2bfloat162_rn(v.x, v.y);
    d[1] = __floats2bfloat162_rn(v.z, v.w);
}

// ---------------- embedding gather ----------------
__global__ void embed_kernel(const int* __restrict__ target, const float* __restrict__ emb) {
    int i = blockIdx.x * blockDim.x + threadIdx.x;
    if (i < CB * CT * CE) {
        int bt = i / CE, e = i - bt * CE;
        gb_emb[i] = __float2bfloat16(emb[(size_t)target[bt] * CE + e]);
    }
}

// ---------------- mma / ldmatrix / cp.async helpers ----------------
__device__ __forceinline__ void mma_bf16(float* d, const unsigned* a, const unsigned* b) {
    asm volatile(
        "mma.sync.aligned.m16n8k16.row.col.f32.bf16.bf16.f32 "
        "{%0,%1,%2,%3}, {%4,%5,%6,%7}, {%8,%9}, {%0,%1,%2,%3};"
        : "+f"(d[0]), "+f"(d[1]), "+f"(d[2]), "+f"(d[3])
        : "r"(a[0]), "r"(a[1]), "r"(a[2]), "r"(a[3]), "r"(b[0]), "r"(b[1]));
}

__device__ __forceinline__ void ldsm4(unsigned& r0, unsigned& r1, unsigned& r2, unsigned& r3,
                                      unsigned addr) {
    asm volatile("ldmatrix.sync.aligned.m8n8.x4.shared.b16 {%0,%1,%2,%3}, [%4];"
        : "=r"(r0), "=r"(r1), "=r"(r2), "=r"(r3) : "r"(addr));
}

__device__ __forceinline__ void ldsm2(unsigned& r0, unsigned& r1, unsigned addr) {
    asm volatile("ldmatrix.sync.aligned.m8n8.x2.shared.b16 {%0,%1}, [%2];"
        : "=r"(r0), "=r"(r1) : "r"(addr));
}

__device__ __forceinline__ void cpa16(unsigned dst, const void* src) {
    asm volatile("cp.async.ca.shared.global [%0], [%1], 16;" :: "r"(dst), "l"(src));
}

__device__ __forceinline__ unsigned smem_u32(const void* p) {
    unsigned a;
    asm("{ .reg .u64 t; cvta.to.shared.u64 t, %1; cvt.u32.u64 %0, t; }" : "=r"(a) : "l"(p));
    return a;
}

// ---------------- bf16 tensor-core NT GEMM ----------------
// 4-stage cp.async pipeline, prefetch depth 2 (wait_group 2), ldmatrix fragments.
#define BG_DYN (4 * 16384)

template<bool OB>
__global__ __launch_bounds__(256, 2) void bgemm_nt(
    const __nv_bfloat16* __restrict__ A, const __nv_bfloat16* __restrict__ Bm,
    const float* __restrict__ bias, void* __restrict__ Cv,
    int K, int lda, int ldb, int ldc, long sA, long sB, long sC)
{
    extern __shared__ unsigned bsm_dyn[];
    unsigned baseS = smem_u32(bsm_dyn);
    const __nv_bfloat16* Ab = A + (size_t)blockIdx.z * sA + (size_t)(blockIdx.x * 128) * lda;
    const __nv_bfloat16* Bb = Bm + (size_t)blockIdx.z * sB + (size_t)(blockIdx.y * 128) * ldb;
    int tid = threadIdx.x;
    int warp = tid >> 5, lane = tid & 31;
    int wm = (warp >> 2) * 64, wn = (warp & 3) * 32;
    int lr = lane >> 2, lq = lane & 3;

    int r0 = tid >> 2, g0 = tid & 3;
    unsigned woff = (unsigned)(r0 * 64 + ((g0 ^ ((r0 >> 1) & 3)) << 4));
    const __nv_bfloat16* srcA0 = Ab + (size_t)r0 * lda + g0 * 8;
    const __nv_bfloat16* srcA1 = srcA0 + (size_t)64 * lda;
    const __nv_bfloat16* srcB0 = Bb + (size_t)r0 * ldb + g0 * 8;
    const __nv_bfloat16* srcB1 = srcB0 + (size_t)64 * ldb;

    int lt = lane >> 3, rr = lane & 7;
    int gAoff = lt >> 1;
    unsigned rowA64[4]; unsigned swzA[4];
    #pragma unroll
    for (int mi = 0; mi < 4; mi++) {
        int row = wm + mi * 16 + ((lt & 1) << 3) + rr;
        rowA64[mi] = row * 64;
        swzA[mi] = (row >> 1) & 3;
    }
    int gBoff = lt & 1;
    unsigned rowB64[2]; unsigned swzB[2];
    #pragma unroll
    for (int np = 0; np < 2; np++) {
        int row = wn + np * 16 + ((lt >> 1) << 3) + rr;
        rowB64[np] = row * 64;
        swzB[np] = (row >> 1) & 3;
    }

    float acc[4][4][4];
    #pragma unroll
    for (int mi = 0; mi < 4; mi++)
        #pragma unroll
        for (int ni = 0; ni < 4; ni++)
            #pragma unroll
            for (int r = 0; r < 4; r++) acc[mi][ni][r] = 0.f;

#define STAGE_LOAD(st, kt) do { \
        unsigned sb_ = baseS + (unsigned)(st) * 16384u; \
        cpa16(sb_ + woff, srcA0 + (kt)); \
        cpa16(sb_ + woff + 4096u, srcA1 + (kt)); \
        cpa16(sb_ + 8192u + woff, srcB0 + (kt)); \
        cpa16(sb_ + 8192u + woff + 4096u, srcB1 + (kt)); \
        asm volatile("cp.async.commit_group;"); } while (0)

    int nt = K / 32;
    STAGE_LOAD(0, 0);
    STAGE_LOAD(1, 32);
    STAGE_LOAD(2, 64);

    for (int it = 0; it < nt; it++) {
        int rem = nt - 1 - it;
        if (rem >= 2)      asm volatile("cp.async.wait_group 2;");
        else if (rem == 1) asm volatile("cp.async.wait_group 1;");
        else               asm volatile("cp.async.wait_group 0;");
        __syncthreads();
        if (it + 3 < nt) STAGE_LOAD((it + 3) & 3, (it + 3) * 32);

        unsigned stA = baseS + (unsigned)(it & 3) * 16384u;
        unsigned stB = stA + 8192u;
        #pragma unroll
        for (int ks = 0; ks < 2; ks++) {
            const int kg = ks * 2;
            unsigned a[4][4], b[4][2];
            #pragma unroll
            for (int mi = 0; mi < 4; mi++)
                ldsm4(a[mi][0], a[mi][1], a[mi][2], a[mi][3],
                      stA + rowA64[mi] + ((unsigned)((kg + gAoff) ^ swzA[mi]) << 4));
            #pragma unroll
            for (int np = 0; np < 2; np++)
                ldsm4(b[2 * np][0], b[2 * np][1], b[2 * np + 1][0], b[2 * np + 1][1],
                      stB + rowB64[np] + ((unsigned)((kg + gBoff) ^ swzB[np]) << 4));
            #pragma unroll
            for (int mi = 0; mi < 4; mi++)
                #pragma unroll
                for (int ni = 0; ni < 4; ni++)
                    mma_bf16(acc[mi][ni], a[mi], b[ni]);
        }
    }
#undef STAGE_LOAD

    int m0 = blockIdx.x * 128, n0 = blockIdx.y * 128;
    #pragma unroll
    for (int mi = 0; mi < 4; mi++) {
        #pragma unroll
        for (int ni = 0; ni < 4; ni++) {
            int m = m0 + wm + mi * 16 + lr;
            int n = n0 + wn + ni * 8 + lq * 2;
            float b0 = bias ? bias[n] : 0.f;
            float b1 = bias ? bias[n + 1] : 0.f;
            float v00 = acc[mi][ni][0] + b0, v01 = acc[mi][ni][1] + b1;
            float v10 = acc[mi][ni][2] + b0, v11 = acc[mi][ni][3] + b1;
            if (OB) {
                __nv_bfloat16* Cb = (__nv_bfloat16*)Cv + (size_t)blockIdx.z * sC;
                *(__nv_bfloat162*)(Cb + (size_t)m * ldc + n) = __floats2bfloat162_rn(v00, v01);
                *(__nv_bfloat162*)(Cb + (size_t)(m + 8) * ldc + n) = __floats2bfloat162_rn(v10, v11);
            } else {
                float* Cb = (float*)Cv + (size_t)blockIdx.z * sC;
                *(float2*)(Cb + (size_t)m * ldc + n) = make_float2(v00, v01);
                *(float2*)(Cb + (size_t)(m + 8) * ldc + n) = make_float2(v10, v11);
            }
        }
    }
}

// ---------------- tensor-core persistent GRU ----------------
#define GNB 32
#define GKP 1032
#define GRU_SMEM (104 * GKP * 2 + 2 * 96 * 9 * 4)

__global__ __launch_bounds__(256) void gru_mma_kernel(
    const float* __restrict__ gi, const float* __restrict__ Wh,
    const float* __restrict__ bh, float* __restrict__ hout,
    __nv_bfloat16* __restrict__ houtb, int ldo)
{
    extern __shared__ __nv_bfloat16 dyn[];
    __nv_bfloat16* whs = dyn;                       // [96][GKP]
    __nv_bfloat16* hs  = dyn + 96 * GKP;            // [8][GKP]
    float* gates = (float*)(dyn + 104 * GKP);       // [96][9]
    float* gis   = gates + 96 * 9;                  // [96][9]
    int tid = threadIdx.x, warp = tid >> 5, lane = tid & 31;
    int j0 = blockIdx.x * 32;

    for (int idx = tid; idx < 96 * CH; idx += 256) {
        int row = idx >> 10, k = idx & (CH - 1);
        int gate = row >> 5, u = row & 31;
        whs[row * GKP + k] = __float2bfloat16(Wh[(size_t)(gate * CH + j0 + u) * CH + k]);
    }
    for (int idx = tid; idx < CB * GKP; idx += 256) hs[idx] = __float2bfloat16(0.f);

    int j = tid & 31, b = tid >> 5;
    float bhr = bh[j0 + j], bhz = bh[CH + j0 + j], bhn = bh[2 * CH + j0 + j];
    float hprev = 0.f;

    unsigned whb = (unsigned)__cvta_generic_to_shared(whs);
    unsigned hsb = (unsigned)__cvta_generic_to_shared(hs);
    int lt = lane >> 3, rr = lane & 7;
    unsigned aAddr = whb + (unsigned)(((warp << 4) + ((lt & 1) << 3) + rr) * GKP
                                      + ((lt >> 1) << 3)) * 2u;
    int ln = lane & 15;
    unsigned bAddr = hsb + (unsigned)((ln & 7) * GKP + ((ln >> 3) << 3)) * 2u;
    __syncthreads();

    for (int t = 0; t < CT; t++) {
        if (warp < 6) {
            float acc[4][4];
            #pragma unroll
            for (int i = 0; i < 4; i++)
                #pragma unroll
                for (int r = 0; r < 4; r++) acc[i][r] = 0.f;
            #pragma unroll 8
            for (int ks = 0; ks < 64; ks++) {
                unsigned av[4], bv[2];
                ldsm4(av[0], av[1], av[2], av[3], aAddr + ks * 32u);
                ldsm2(bv[0], bv[1], bAddr + ks * 32u);
                mma_bf16(acc[ks & 3], av, bv);
            }
            float c0 = acc[0][0] + acc[1][0] + acc[2][0] + acc[3][0];
            float c1 = acc[0][1] + acc[1][1] + acc[2][1] + acc[3][1];
            float c2 = acc[0][2] + acc[1][2] + acc[2][2] + acc[3][2];
            float c3 = acc[0][3] + acc[1][3] + acc[2][3] + acc[3][3];
            int r_ = lane >> 2, q = lane & 3;
            int rowb = (warp << 4) + r_;
            gates[rowb * 9 + 2 * q]           = c0;
            gates[rowb * 9 + 2 * q + 1]       = c1;
            gates[(rowb + 8) * 9 + 2 * q]     = c2;
            gates[(rowb + 8) * 9 + 2 * q + 1] = c3;
        } else {
            for (int idx = tid - 192; idx < 768; idx += 64) {
                int g = idx >> 8, rem = idx & 255, jj = rem & 31, bb = rem >> 5;
                gis[(g * 32 + jj) * 9 + bb] =
                    gi[(size_t)(bb * CT + t) * C3H + g * CH + j0 + jj];
            }
        }
        __syncthreads();

        float rg = 1.f / (1.f + expf(-(gis[j * 9 + b] + gates[j * 9 + b] + bhr)));
        float zg = 1.f / (1.f + expf(-(gis[(32 + j) * 9 + b] + gates[(32 + j) * 9 + b] + bhz)));
        float ng = tanhf(gis[(64 + j) * 9 + b] + rg * (gates[(64 + j) * 9 + b] + bhn));
        float hn = (1.f - zg) * ng + zg * hprev;
        hprev = hn;
        // broadcast first: its visibility latency is on the critical path
        g_hbf[(t + 1) & 1][b * CH + j0 + j] = __float2bfloat16(hn);
        if (hout) hout[(size_t)(b * CT + t) * CH + j0 + j] = hn;
        houtb[(size_t)(b * CT + t) * ldo + j0 + j] = __float2bfloat16(hn);

        grid_sync_all(GNB);

        const __nv_bfloat16* hb = (const __nv_bfloat16*)g_hbf[(t + 1) & 1];
        for (int idx = tid; idx < CB * CH / 8; idx += 256) {
            int bb = idx >> 7, kk = (idx & 127) << 3;
            *(uint4*)(hs + bb * GKP + kk) = *(const uint4*)(hb + bb * CH + kk);
        }
        __syncthreads();
    }
}

// ---------------- small attention scores (one warp per dot) ----------------
__global__ void attn_scores_kernel(const float* __restrict__ q, const float* __restrict__ proj,
                                   float* __restrict__ out, int N) {
    int gw = (blockIdx.x * blockDim.x + threadIdx.x) >> 5;
    int lane = threadIdx.x & 31;
    if (gw >= CB * CT * N) return;
    int n = gw % N;
    int bt = gw / N;
    int b = bt / CT;
    const float* qp = q + (size_t)bt * CH;
    const float* pp = proj + (size_t)(b * N + n) * CH;
    float acc = 0.f;
    for (int k = lane * 4; k < CH; k += 128) {
        float4 qa = *(const float4*)(qp + k);
        float4 pa = *(const float4*)(pp + k);
        acc += qa.x * pa.x + qa.y * pa.y + qa.z * pa.z + qa.w * pa.w;
    }
    #pragma unroll
    for (int o = 16; o; o >>= 1) acc += __shfl_xor_sync(0xffffffffu, acc, o);
    if (lane == 0) out[gw] = acc;
}

// ---------------- fused masked softmaxes + hierarchical combine (bf16 out) ----------------
__global__ __launch_bounds__(256) void combine_kernel(
    const int* __restrict__ s_len, const int* __restrict__ u_len, const int* __restrict__ w_len,
    const int* __restrict__ seg, const int* __restrict__ utt)
{
    int bt = blockIdx.x, b = bt / CT, tid = threadIdx.x;
    __shared__ float ss[CS];
    __shared__ float su[CU];
    __shared__ float sw[CW];
    __shared__ float red[32];
    int sl = s_len[b], ul = u_len[b], wl = w_len[b];

    if (tid < 32) {
        float v = (tid < sl) ? g_sc_s[bt * CS + tid] : -INFINITY;
        float m = v;
        #pragma unroll
        for (int o = 16; o; o >>= 1) m = fmaxf(m, __shfl_xor_sync(0xffffffffu, m, o));
        float e = (tid < sl) ? expf(v - m) : 0.f;
        float s = e;
        #pragma unroll
        for (int o = 16; o; o >>= 1) s += __shfl_xor_sync(0xffffffffu, s, o);
        if (tid < CS) ss[tid] = e / s;
    }
    float uv = (tid < CU && tid < ul) ? g_sc_u[bt * CU + tid] : -INFINITY;
    float um = blockReduceMax256(uv, red);
    float ue = (tid < CU && tid < ul) ? expf(uv - um) : 0.f;
    float us = blockReduceSum256(ue, red);
    if (tid < CU) su[tid] = ue / us;
    float wv[4], we[4];
    float wm = -INFINITY;
    #pragma unroll
    for (int i = 0; i < 4; i++) {
        int idx = tid + 256 * i;
        wv[i] = (idx < wl) ? g_sc_w[(size_t)bt * CW + idx] : -INFINITY;
        wm = fmaxf(wm, wv[i]);
    }
    wm = blockReduceMax256(wm, red);
    float wsum = 0.f;
    #pragma unroll
    for (int i = 0; i < 4; i++) {
        int idx = tid + 256 * i;
        we[i] = (idx < wl) ? expf(wv[i] - wm) : 0.f;
        wsum += we[i];
    }
    wsum = blockReduceSum256(wsum, red);
    #pragma unroll
    for (int i = 0; i < 4; i++) sw[tid + 256 * i] = we[i] / wsum;
    __syncthreads();
    if (tid < CU) {
        float v2 = (tid < ul) ? ss[seg[b * CU + tid]] * su[tid] : 0.f;
        su[tid] = v2;
    }
    __syncthreads();
    float pv[4];
    #pragma unroll
    for (int i = 0; i < 4; i++) {
        int idx = tid + 256 * i;
        pv[i] = (idx < wl) ? su[utt[b * CW + idx]] * sw[idx] : 0.f;
    }
    float pm = fmaxf(fmaxf(pv[0], pv[1]), fmaxf(pv[2], pv[3]));
    pm = blockReduceMax256(pm, red);
    float pe[4];
    float psum = 0.f;
    #pragma unroll
    for (int i = 0; i < 4; i++) { pe[i] = expf(pv[i] - pm); psum += pe[i]; }
    psum = blockReduceSum256(psum, red);
    #pragma unroll
    for (int i = 0; i < 4; i++)
        gb_suw[(size_t)bt * CW + tid + 256 * i] = __float2bfloat16(pe[i] / psum);
}

// ---------------- per-batch transpose of w_output -> bf16 [B,2M,W] ----------------
__global__ void transpose_w_kernel(const float* __restrict__ wo) {
    __shared__ float tile[32][33];
    int b = blockIdx.z;
    int w0 = blockIdx.x * 32, m0 = blockIdx.y * 32;
    int x = threadIdx.x, y = threadIdx.y;
    #pragma unroll
    for (int i = 0; i < 32; i += 8)
        tile[y + i][x] = wo[((size_t)b * CW + (w0 + y + i)) * CM2 + m0 + x];
    __syncthreads();
    #pragma unroll
    for (int i = 0; i < 32; i += 8)
        gb_wT[((size_t)b * CM2 + (m0 + y + i)) * CW + w0 + x] = __float2bfloat16(tile[x][y + i]);
}

// ---------------- in-place log_softmax: single-pass online max+sum ----------------
__global__ __launch_bounds__(256) void logsoftmax_kernel(float* __restrict__ out) {
    __shared__ float redm[8];
    __shared__ float reds[8];
    int row = blockIdx.x, tid = threadIdx.x;
    float* p = out + (size_t)row * CV;
    float m = -INFINITY, s = 0.f;
    for (int i = tid; i < CV; i += 256) {
        float v = p[i];
        if (v > m) { s *= expf(m - v); m = v; }
        s += expf(v - m);
    }
    #pragma unroll
    for (int o = 16; o; o >>= 1) {
        float om = __shfl_xor_sync(0xffffffffu, m, o);
        float os = __shfl_xor_sync(0xffffffffu, s, o);
        float M = fmaxf(m, om);
        s = s * expf(m - M) + os * expf(om - M);
        m = M;
    }
    if ((tid & 31) == 0) { redm[tid >> 5] = m; reds[tid >> 5] = s; }
    __syncthreads();
    if (tid < 32) {
        float mm = (tid < 8) ? redm[tid] : -INFINITY;
        float sv = (tid < 8) ? reds[tid] : 0.f;
        #pragma unroll
        for (int o = 4; o; o >>= 1) {
            float om = __shfl_xor_sync(0xffffffffu, mm, o);
            float os = __shfl_xor_sync(0xffffffffu, sv, o);
            float M = fmaxf(mm, om);
            float e1 = (sv > 0.f) ? sv * expf(mm - M) : 0.f;
            float e2 = (os > 0.f) ? os * expf(om - M) : 0.f;
            sv = e1 + e2;
            mm = M;
        }
        if (tid == 0) { redm[0] = mm; reds[0] = sv; }
    }
    __syncthreads();
    float lse = redm[0] + logf(reds[0]);
    for (int i = tid; i < CV; i += 256) p[i] -= lse;
}

// ---------------- launch ----------------
extern "C" void kernel_launch(void* const* d_in, const int* in_sizes, int n_in,
                              void* d_out, int out_size) {
    const int*   target   = (const int*)d_in[0];
    const float* embedding= (const float*)d_in[1];
    const float* W_ih0    = (const float*)d_in[2];
    const float* W_hh0    = (const float*)d_in[3];
    const float* b_ih0    = (const float*)d_in[4];
    const float* b_hh0    = (const float*)d_in[5];
    const float* W_ih1    = (const float*)d_in[6];
    const float* W_hh1    = (const float*)d_in[7];
    const float* b_ih1    = (const float*)d_in[8];
    const float* b_hh1    = (const float*)d_in[9];
    const float* att_s_w  = (const float*)d_in[10];
    const float* att_s_b  = (const float*)d_in[11];
    const float* att_u_w  = (const float*)d_in[12];
    const float* att_u_b  = (const float*)d_in[13];
    const float* att_w_w  = (const float*)d_in[14];
    const float* att_w_b  = (const float*)d_in[15];
    const float* out_w    = (const float*)d_in[16];
    const float* out_b    = (const float*)d_in[17];
    const float* s_output = (const float*)d_in[18];
    const float* u_output = (const float*)d_in[19];
    const float* w_output = (const float*)d_in[20];
    const int*   s_len    = (const int*)d_in[21];
    const int*   u_len    = (const int*)d_in[22];
    const int*   w_len    = (const int*)d_in[23];
    const int*   seg      = (const int*)d_in[24];
    const int*   utt      = (const int*)d_in[25];
    float* out = (float*)d_out;

    float *p_gi, *p_rnn, *p_ps, *p_pu, *p_scs, *p_scu, *p_scw;
    cudaGetSymbolAddress((void**)&p_gi, g_gi);
    cudaGetSymbolAddress((void**)&p_rnn, g_rnn);
    cudaGetSymbolAddress((void**)&p_ps, g_proj_s);
    cudaGetSymbolAddress((void**)&p_pu, g_proj_u);
    cudaGetSymbolAddress((void**)&p_scs, g_sc_s);
    cudaGetSymbolAddress((void**)&p_scu, g_sc_u);
    cudaGetSymbolAddress((void**)&p_scw, g_sc_w);
    __nv_bfloat16 *b_h1, *b_feat, *b_suw, *b_sout, *b_uout, *b_wout,
                  *b_wT, *b_pw, *b_Wih0, *b_Wih1, *b_atts, *b_attu, *b_attw, *b_outw, *b_emb;
    cudaGetSymbolAddress((void**)&b_emb, gb_emb);
    cudaGetSymbolAddress((void**)&b_h1, gb_h1);
    cudaGetSymbolAddress((void**)&b_feat, gb_feat);
    cudaGetSymbolAddress((void**)&b_suw, gb_suw);
    cudaGetSymbolAddress((void**)&b_sout, gb_sout);
    cudaGetSymbolAddress((void**)&b_uout, gb_uout);
    cudaGetSymbolAddress((void**)&b_wout, gb_wout);
    cudaGetSymbolAddress((void**)&b_wT, gb_wT);
    cudaGetSymbolAddress((void**)&b_pw, gb_pw);
    cudaGetSymbolAddress((void**)&b_Wih0, gb_Wih0);
    cudaGetSymbolAddress((void**)&b_Wih1, gb_Wih1);
    cudaGetSymbolAddress((void**)&b_atts, gb_atts);
    cudaGetSymbolAddress((void**)&b_attu, gb_attu);
    cudaGetSymbolAddress((void**)&b_attw, gb_attw);
    cudaGetSymbolAddress((void**)&b_outw, gb_outw);

    cudaFuncSetAttribute(gru_mma_kernel,
                         cudaFuncAttributeMaxDynamicSharedMemorySize, GRU_SMEM);
    cudaFuncSetAttribute(bgemm_nt<true>,
                         cudaFuncAttributeMaxDynamicSharedMemorySize, BG_DYN);
    cudaFuncSetAttribute(bgemm_nt<false>,
                         cudaFuncAttributeMaxDynamicSharedMemorySize, BG_DYN);

    // 1. merged fp32->bf16 conversions
    convert_all_kernel<<<(unsigned)(SEG8 / 256), 256>>>(
        W_ih0, W_ih1, att_s_w, att_u_w, att_w_w, out_w, s_output, u_output, w_output);
    // 2. embedding gather
    embed_kernel<<<(CB * CT * CE + 255) / 256, 256>>>(target, embedding);
    // 3. proj_w (independent of GRU)
    bgemm_nt<true><<<dim3((CB * CW) / 128, CH / 128, 1), 256, BG_DYN>>>(b_wout, b_attw, att_w_b, b_pw,
        CM2, CM2, CM2, CH, 0, 0, 0);
    // 4. gi0 = emb @ W_ih0^T + b_ih0
    bgemm_nt<false><<<dim3((CB * CT) / 128, C3H / 128, 1), 256, BG_DYN>>>(b_emb, b_Wih0, b_ih0, p_gi,
        CE, CE, CE, C3H, 0, 0, 0);
    // 5. atts projection (independent; placed here so launch #6 = gru0 for ncu -s 5)
    bgemm_nt<false><<<dim3((CB * CS) / 128, CH / 128, 1), 256, BG_DYN>>>(b_sout, b_atts, att_s_b, p_ps,
        CM, CM, CM, CH, 0, 0, 0);
    // 6. GRU layer 0 (tensor-core persistent) -> bf16 gb_h1   [ncu capture target]
    gru_mma_kernel<<<GNB, 256, GRU_SMEM>>>(p_gi, W_hh0, b_hh0, nullptr, b_h1, CH);
    // 7. gi1 = h1 @ W_ih1^T + b_ih1
    bgemm_nt<false><<<dim3((CB * CT) / 128, C3H / 128, 1), 256, BG_DYN>>>(b_h1, b_Wih1, b_ih1, p_gi,
        CH, CH, CH, C3H, 0, 0, 0);
    // 8. GRU layer 1 -> fp32 rnn + bf16 directly into feat[:, 1024:]
    gru_mma_kernel<<<GNB, 256, GRU_SMEM>>>(p_gi, W_hh1, b_hh1, p_rnn, b_feat + CM2, CF);
    // 9. attu projection
    bgemm_nt<false><<<dim3((CB * CU) / 128, CH / 128, 1), 256, BG_DYN>>>(b_uout, b_attu, att_u_b, p_pu,
        CM, CM, CM, CH, 0, 0, 0);
    // 10. raw scores
    attn_scores_kernel<<<(CB * CT * CS) / 8, 256>>>(p_rnn, p_ps, p_scs, CS);
    attn_scores_kernel<<<(CB * CT * CU) / 8, 256>>>(p_rnn, p_pu, p_scu, CU);
    bgemm_nt<false><<<dim3(CT / 128, CW / 128, CB), 256, BG_DYN>>>(b_feat + CM2, b_pw, nullptr, p_scw,
        CH, CF, CH, CW, (long)CT * CF, (long)CW * CH, (long)CT * CW);
    // 11. masked softmaxes + hierarchical combine + final softmax
    combine_kernel<<<CB * CT, 256>>>(s_len, u_len, w_len, seg, utt);
    // 12. context = suw @ w_output -> bf16 feat[:, :1024]
    transpose_w_kernel<<<dim3(CW / 32, CM2 / 32, CB), dim3(32, 8)>>>(w_output);
    bgemm_nt<true><<<dim3(CT / 128, CM2 / 128, CB), 256, BG_DYN>>>(b_suw, b_wT, nullptr, b_feat,
        CW, CW, CW, CF, (long)CT * CW, (long)CM2 * CW, (long)CT * CF);
    // 13. logits = feat @ out_w^T + out_b -> d_out (fp32)
    bgemm_nt<false><<<dim3((CB * CT) / 128, CV / 128, 1), 256, BG_DYN>>>(b_feat, b_outw, out_b, out,
        CF, CF, CF, CV, 0, 0, 0);
    // 14. in-place log_softmax (single-pass online)
    logsoftmax_kernel<<<CB * CT, 256>>>(out);
}

// round 14
// speedup vs baseline: 1.0956x; 1.0956x over previous
#include <cuda_runtime.h>
#include <cuda_bf16.h>
#include <math.h>

// ---------------- problem constants ----------------
#define CB 8       // batch
#define CT 128     // time
#define CE 512     // embed dim
#define CH 1024    // hidden
#define CM 512     // mem hidden
#define CM2 1024   // 2*M
#define CS 16
#define CU 128
#define CW 1024
#define CV 32000
#define C3H 3072
#define CF 2048    // H + 2M

// ---------------- fp32 scratch ----------------
__device__ float g_gi[CB * CT * C3H];
__device__ float g_rnn[CB * CT * CH];
__device__ float g_proj_s[CB * CS * CH];
__device__ float g_proj_u[CB * CU * CH];
__device__ float g_sc_s[CB * CT * CS];
__device__ float g_sc_u[CB * CT * CU];
__device__ float g_sc_w[CB * CT * CW];
__device__ unsigned g_bar_arr = 0;
__device__ unsigned g_bar_gen = 0;

// ---------------- bf16 scratch ----------------
__device__ __nv_bfloat16 gb_emb[CB * CT * CE];
__device__ __nv_bfloat16 gb_h1[CB * CT * CH];
__device__ __nv_bfloat16 gb_feat[CB * CT * CF];
__device__ __nv_bfloat16 gb_suw[CB * CT * CW];
__device__ __nv_bfloat16 gb_sout[CB * CS * CM];
__device__ __nv_bfloat16 gb_uout[CB * CU * CM];
__device__ __nv_bfloat16 gb_wout[CB * CW * CM2];
__device__ __nv_bfloat16 gb_wT[CB * CM2 * CW];
__device__ __nv_bfloat16 gb_pw[CB * CW * CH];
__device__ __nv_bfloat16 gb_Wih0[C3H * CE];
__device__ __nv_bfloat16 gb_Wih1[C3H * CH];
__device__ __nv_bfloat16 gb_atts[CH * CM];
__device__ __nv_bfloat16 gb_attu[CH * CM];
__device__ __nv_bfloat16 gb_attw[CH * CM2];
__device__ __nv_bfloat16 gb_outw[(size_t)CV * CF];   // 131 MB
__device__ __nv_bfloat16 g_hbf[2][CB * CH];          // GRU h broadcast (double buffer)

// ---------------- grid barrier (R11 atomic-poll version — proven fastest) ----------------
__device__ __forceinline__ void grid_sync_all(unsigned nb) {
    __threadfence();
    __syncthreads();
    if (threadIdx.x == 0) {
        unsigned gen = atomicAdd(&g_bar_gen, 0u);
        if (atomicAdd(&g_bar_arr, 1u) == nb - 1u) {
            atomicExch(&g_bar_arr, 0u);
            __threadfence();
            atomicAdd(&g_bar_gen, 1u);
        } else {
            while (atomicAdd(&g_bar_gen, 0u) == gen) { __nanosleep(32); }
        }
    }
    __syncthreads();
}

// ---------------- block reductions (256 threads) ----------------
__device__ __forceinline__ float blockReduceMax256(float v, float* red) {
    #pragma unroll
    for (int o = 16; o; o >>= 1) v = fmaxf(v, __shfl_xor_sync(0xffffffffu, v, o));
    if ((threadIdx.x & 31) == 0) red[threadIdx.x >> 5] = v;
    __syncthreads();
    if (threadIdx.x < 32) {
        float r = (threadIdx.x < 8) ? red[threadIdx.x] : -INFINITY;
        #pragma unroll
        for (int o = 4; o; o >>= 1) r = fmaxf(r, __shfl_xor_sync(0xffffffffu, r, o));
        if (threadIdx.x == 0) red[0] = r;
    }
    __syncthreads();
    float out = red[0];
    __syncthreads();
    return out;
}

__device__ __forceinline__ float blockReduceSum256(float v, float* red) {
    #pragma unroll
    for (int o = 16; o; o >>= 1) v += __shfl_xor_sync(0xffffffffu, v, o);
    if ((threadIdx.x & 31) == 0) red[threadIdx.x >> 5] = v;
    __syncthreads();
    if (threadIdx.x < 32) {
        float r = (threadIdx.x < 8) ? red[threadIdx.x] : 0.f;
        #pragma unroll
        for (int o = 4; o; o >>= 1) r += __shfl_xor_sync(0xffffffffu, r, o);
        if (threadIdx.x == 0) red[0] = r;
    }
    __syncthreads();
    float out = red[0];
    __syncthreads();
    return out;
}

// ---------------- single merged fp32->bf16 convert (9 segments) ----------------
#define SEG0 (C3H * CE / 4)
#define SEG1 (SEG0 + C3H * CH / 4)
#define SEG2 (SEG1 + CH * CM / 4)
#define SEG3 (SEG2 + CH * CM / 4)
#define SEG4 (SEG3 + CH * CM2 / 4)
#define SEG5 (SEG4 + (size_t)CV * CF / 4)
#define SEG6 (SEG5 + CB * CS * CM / 4)
#define SEG7 (SEG6 + CB * CU * CM / 4)
#define SEG8 (SEG7 + CB * CW * CM2 / 4)

__global__ void convert_all_kernel(
    const float* __restrict__ s0, const float* __restrict__ s1,
    const float* __restrict__ s2, const float* __restrict__ s3,
    const float* __restrict__ s4, const float* __restrict__ s5,
    const float* __restrict__ s6, const float* __restrict__ s7,
    const float* __restrict__ s8)
{
    size_t i4 = (size_t)blockIdx.x * 256 + threadIdx.x;
    const float* src; __nv_bfloat16* dst; size_t off;
    if      (i4 < SEG0) { src = s0; dst = gb_Wih0; off = i4; }
    else if (i4 < SEG1) { src = s1; dst = gb_Wih1; off = i4 - SEG0; }
    else if (i4 < SEG2) { src = s2; dst = gb_atts; off = i4 - SEG1; }
    else if (i4 < SEG3) { src = s3; dst = gb_attu; off = i4 - SEG2; }
    else if (i4 < SEG4) { src = s4; dst = gb_attw; off = i4 - SEG3; }
    else if (i4 < SEG5) { src = s5; dst = gb_outw; off = i4 - SEG4; }
    else if (i4 < SEG6) { src = s6; dst = gb_sout; off = i4 - SEG5; }
    else if (i4 < SEG7) { src = s7; dst = gb_uout; off = i4 - SEG6; }
    else if (i4 < SEG8) { src = s8; dst = gb_wout; off = i4 - SEG7; }
    else return;
    float4 v = ((const float4*)src)[off];
    __nv_bfloat162* d = (__nv_bfloat162*)(dst + off * 4);
    d[0] = __floats2bfloat162_rn(v.x, v.y);
    d[1] = __floats2bfloat162_rn(v.z, v.w);
}

// ---------------- embedding gather ----------------
__global__ void embed_kernel(const int* __restrict__ target, const float* __restrict__ emb) {
    int i = blockIdx.x * blockDim.x + threadIdx.x;
    if (i < CB * CT * CE) {
        int bt = i / CE, e = i - bt * CE;
        gb_emb[i] = __float2bfloat16(emb[(size_t)target[bt] * CE + e]);
    }
}

// ---------------- mma / ldmatrix / cp.async helpers ----------------
__device__ __forceinline__ void mma_bf16(float* d, const unsigned* a, const unsigned* b) {
    asm volatile(
        "mma.sync.aligned.m16n8k16.row.col.f32.bf16.bf16.f32 "
        "{%0,%1,%2,%3}, {%4,%5,%6,%7}, {%8,%9}, {%0,%1,%2,%3};"
        : "+f"(d[0]), "+f"(d[1]), "+f"(d[2]), "+f"(d[3])
        : "r"(a[0]), "r"(a[1]), "r"(a[2]), "r"(a[3]), "r"(b[0]), "r"(b[1]));
}

__device__ __forceinline__ void ldsm4(unsigned& r0, unsigned& r1, unsigned& r2, unsigned& r3,
                                      unsigned addr) {
    asm volatile("ldmatrix.sync.aligned.m8n8.x4.shared.b16 {%0,%1,%2,%3}, [%4];"
        : "=r"(r0), "=r"(r1), "=r"(r2), "=r"(r3) : "r"(addr));
}

__device__ __forceinline__ void ldsm2(unsigned& r0, unsigned& r1, unsigned addr) {
    asm volatile("ldmatrix.sync.aligned.m8n8.x2.shared.b16 {%0,%1}, [%2];"
        : "=r"(r0), "=r"(r1) : "r"(addr));
}

__device__ __forceinline__ void cpa16(unsigned dst, const void* src) {
    asm volatile("cp.async.ca.shared.global [%0], [%1], 16;" :: "r"(dst), "l"(src));
}

__device__ __forceinline__ unsigned smem_u32(const void* p) {
    unsigned a;
    asm("{ .reg .u64 t; cvta.to.shared.u64 t, %1; cvt.u32.u64 %0, t; }" : "=r"(a) : "l"(p));
    return a;
}

// ---------------- bf16 tensor-core NT GEMM ----------------
// KT=64 stages (canonical SW128 swizzle: 128B rows, g ^= row&7), 3 stages x 32KB,
// prefetch depth 1, ldmatrix fragments, 8 warps (2M x 4N), warp tile 64x32.
// Requires K%64==0, K>=128.
#define BG_DYN (3 * 32768)

template<bool OB>
__global__ __launch_bounds__(256, 2) void bgemm_nt(
    const __nv_bfloat16* __restrict__ A, const __nv_bfloat16* __restrict__ Bm,
    const float* __restrict__ bias, void* __restrict__ Cv,
    int K, int lda, int ldb, int ldc, long sA, long sB, long sC)
{
    extern __shared__ unsigned bsm_dyn[];
    unsigned baseS = smem_u32(bsm_dyn);
    const __nv_bfloat16* Ab = A + (size_t)blockIdx.z * sA + (size_t)(blockIdx.x * 128) * lda;
    const __nv_bfloat16* Bb = Bm + (size_t)blockIdx.z * sB + (size_t)(blockIdx.y * 128) * ldb;
    int tid = threadIdx.x;
    int warp = tid >> 5, lane = tid & 31;
    int wm = (warp >> 2) * 64, wn = (warp & 3) * 32;
    int lr = lane >> 2, lq = lane & 3;

    // staging: per thread 4 (row, g) slots per matrix; slot = tid + 256*i
    int r0 = tid >> 3, g0 = tid & 7;                 // rows 0..31 per pass, 4 passes
    unsigned woff0 = (unsigned)(r0 * 128 + ((g0 ^ (r0 & 7)) << 4));
    const __nv_bfloat16* srcA = Ab + (size_t)r0 * lda + g0 * 8;
    const __nv_bfloat16* srcB = Bb + (size_t)r0 * ldb + g0 * 8;

    int lt = lane >> 3, rr = lane & 7;
    int gAoff = lt >> 1;
    unsigned rowA128[4]; unsigned swzA[4];
    #pragma unroll
    for (int mi = 0; mi < 4; mi++) {
        int row = wm + mi * 16 + ((lt & 1) << 3) + rr;
        rowA128[mi] = row * 128;
        swzA[mi] = row & 7;
    }
    int gBoff = lt & 1;
    unsigned rowB128[2]; unsigned swzB[2];
    #pragma unroll
    for (int np = 0; np < 2; np++) {
        int row = wn + np * 16 + ((lt >> 1) << 3) + rr;
        rowB128[np] = row * 128;
        swzB[np] = row & 7;
    }

    float acc[4][4][4];
    #pragma unroll
    for (int mi = 0; mi < 4; mi++)
        #pragma unroll
        for (int ni = 0; ni < 4; ni++)
            #pragma unroll
            for (int r = 0; r < 4; r++) acc[mi][ni][r] = 0.f;

#define STAGE_LOAD(st, kt) do { \
        unsigned sb_ = baseS + (unsigned)(st) * 32768u; \
        _Pragma("unroll") \
        for (int i_ = 0; i_ < 4; i_++) { \
            unsigned o_ = woff0 + (unsigned)i_ * 4096u; \
            size_t ro_ = (size_t)(i_ * 32); \
            cpa16(sb_ + o_, srcA + ro_ * lda + (kt)); \
            cpa16(sb_ + 16384u + o_, srcB + ro_ * ldb + (kt)); \
        } \
        asm volatile("cp.async.commit_group;"); } while (0)

    int nt = K / 64;
    STAGE_LOAD(0, 0);
    STAGE_LOAD(1, 64);

    for (int it = 0; it < nt; it++) {
        if (it + 1 < nt) asm volatile("cp.async.wait_group 1;");
        else             asm volatile("cp.async.wait_group 0;");
        __syncthreads();
        if (it + 2 < nt) {
            int st = (it + 2) % 3, kt = (it + 2) * 64;
            STAGE_LOAD(st, kt);
        }

        unsigned stA = baseS + (unsigned)(it % 3) * 32768u;
        unsigned stB = stA + 16384u;
        #pragma unroll
        for (int ks = 0; ks < 4; ks++) {
            const int kg = ks * 2;
            unsigned a[4][4], b[4][2];
            #pragma unroll
            for (int mi = 0; mi < 4; mi++)
                ldsm4(a[mi][0], a[mi][1], a[mi][2], a[mi][3],
                      stA + rowA128[mi] + ((unsigned)((kg + gAoff) ^ swzA[mi]) << 4));
            #pragma unroll
            for (int np = 0; np < 2; np++)
                ldsm4(b[2 * np][0], b[2 * np][1], b[2 * np + 1][0], b[2 * np + 1][1],
                      stB + rowB128[np] + ((unsigned)((kg + gBoff) ^ swzB[np]) << 4));
            #pragma unroll
            for (int mi = 0; mi < 4; mi++)
                #pragma unroll
                for (int ni = 0; ni < 4; ni++)
                    mma_bf16(acc[mi][ni], a[mi], b[ni]);
        }
    }
#undef STAGE_LOAD

    int m0 = blockIdx.x * 128, n0 = blockIdx.y * 128;
    #pragma unroll
    for (int mi = 0; mi < 4; mi++) {
        #pragma unroll
        for (int ni = 0; ni < 4; ni++) {
            int m = m0 + wm + mi * 16 + lr;
            int n = n0 + wn + ni * 8 + lq * 2;
            float b0 = bias ? bias[n] : 0.f;
            float b1 = bias ? bias[n + 1] : 0.f;
            float v00 = acc[mi][ni][0] + b0, v01 = acc[mi][ni][1] + b1;
            float v10 = acc[mi][ni][2] + b0, v11 = acc[mi][ni][3] + b1;
            if (OB) {
                __nv_bfloat16* Cb = (__nv_bfloat16*)Cv + (size_t)blockIdx.z * sC;
                *(__nv_bfloat162*)(Cb + (size_t)m * ldc + n) = __floats2bfloat162_rn(v00, v01);
                *(__nv_bfloat162*)(Cb + (size_t)(m + 8) * ldc + n) = __floats2bfloat162_rn(v10, v11);
            } else {
                float* Cb = (float*)Cv + (size_t)blockIdx.z * sC;
                *(float2*)(Cb + (size_t)m * ldc + n) = make_float2(v00, v01);
                *(float2*)(Cb + (size_t)(m + 8) * ldc + n) = make_float2(v10, v11);
            }
        }
    }
}

// ---------------- tensor-core persistent GRU ----------------
#define GNB 32
#define GKP 1032
#define GRU_SMEM (104 * GKP * 2 + 2 * 96 * 9 * 4)

__global__ __launch_bounds__(256) void gru_mma_kernel(
    const float* __restrict__ gi, const float* __restrict__ Wh,
    const float* __restrict__ bh, float* __restrict__ hout,
    __nv_bfloat16* __restrict__ houtb, int ldo)
{
    extern __shared__ __nv_bfloat16 dyn[];
    __nv_bfloat16* whs = dyn;                       // [96][GKP]
    __nv_bfloat16* hs  = dyn + 96 * GKP;            // [8][GKP]
    float* gates = (float*)(dyn + 104 * GKP);       // [96][9]
    float* gis   = gates + 96 * 9;                  // [96][9]
    int tid = threadIdx.x, warp = tid >> 5, lane = tid & 31;
    int j0 = blockIdx.x * 32;

    for (int idx = tid; idx < 96 * CH; idx += 256) {
        int row = idx >> 10, k = idx & (CH - 1);
        int gate = row >> 5, u = row & 31;
        whs[row * GKP + k] = __float2bfloat16(Wh[(size_t)(gate * CH + j0 + u) * CH + k]);
    }
    for (int idx = tid; idx < CB * GKP; idx += 256) hs[idx] = __float2bfloat16(0.f);

    int j = tid & 31, b = tid >> 5;
    float bhr = bh[j0 + j], bhz = bh[CH + j0 + j], bhn = bh[2 * CH + j0 + j];
    float hprev = 0.f;

    unsigned whb = (unsigned)__cvta_generic_to_shared(whs);
    unsigned hsb = (unsigned)__cvta_generic_to_shared(hs);
    int lt = lane >> 3, rr = lane & 7;
    unsigned aAddr = whb + (unsigned)(((warp << 4) + ((lt & 1) << 3) + rr) * GKP
                                      + ((lt >> 1) << 3)) * 2u;
    int ln = lane & 15;
    unsigned bAddr = hsb + (unsigned)((ln & 7) * GKP + ((ln >> 3) << 3)) * 2u;
    __syncthreads();

    for (int t = 0; t < CT; t++) {
        if (warp < 6) {
            float acc[4][4];
            #pragma unroll
            for (int i = 0; i < 4; i++)
                #pragma unroll
                for (int r = 0; r < 4; r++) acc[i][r] = 0.f;
            #pragma unroll 8
            for (int ks = 0; ks < 64; ks++) {
                unsigned av[4], bv[2];
                ldsm4(av[0], av[1], av[2], av[3], aAddr + ks * 32u);
                ldsm2(bv[0], bv[1], bAddr + ks * 32u);
                mma_bf16(acc[ks & 3], av, bv);
            }
            float c0 = acc[0][0] + acc[1][0] + acc[2][0] + acc[3][0];
            float c1 = acc[0][1] + acc[1][1] + acc[2][1] + acc[3][1];
            float c2 = acc[0][2] + acc[1][2] + acc[2][2] + acc[3][2];
            float c3 = acc[0][3] + acc[1][3] + acc[2][3] + acc[3][3];
            int r_ = lane >> 2, q = lane & 3;
            int rowb = (warp << 4) + r_;
            gates[rowb * 9 + 2 * q]           = c0;
            gates[rowb * 9 + 2 * q + 1]       = c1;
            gates[(rowb + 8) * 9 + 2 * q]     = c2;
            gates[(rowb + 8) * 9 + 2 * q + 1] = c3;
        } else {
            for (int idx = tid - 192; idx < 768; idx += 64) {
                int g = idx >> 8, rem = idx & 255, jj = rem & 31, bb = rem >> 5;
                gis[(g * 32 + jj) * 9 + bb] =
                    gi[(size_t)(bb * CT + t) * C3H + g * CH + j0 + jj];
            }
        }
        __syncthreads();

        float rg = 1.f / (1.f + expf(-(gis[j * 9 + b] + gates[j * 9 + b] + bhr)));
        float zg = 1.f / (1.f + expf(-(gis[(32 + j) * 9 + b] + gates[(32 + j) * 9 + b] + bhz)));
        float ng = tanhf(gis[(64 + j) * 9 + b] + rg * (gates[(64 + j) * 9 + b] + bhn));
        float hn = (1.f - zg) * ng + zg * hprev;
        hprev = hn;
        g_hbf[(t + 1) & 1][b * CH + j0 + j] = __float2bfloat16(hn);
        if (hout) hout[(size_t)(b * CT + t) * CH + j0 + j] = hn;
        houtb[(size_t)(b * CT + t) * ldo + j0 + j] = __float2bfloat16(hn);

        grid_sync_all(GNB);

        const __nv_bfloat16* hb = (const __nv_bfloat16*)g_hbf[(t + 1) & 1];
        for (int idx = tid; idx < CB * CH / 8; idx += 256) {
            int bb = idx >> 7, kk = (idx & 127) << 3;
            *(uint4*)(hs + bb * GKP + kk) = *(const uint4*)(hb + bb * CH + kk);
        }
        __syncthreads();
    }
}

// ---------------- small attention scores (one warp per dot) ----------------
__global__ void attn_scores_kernel(const float* __restrict__ q, const float* __restrict__ proj,
                                   float* __restrict__ out, int N) {
    int gw = (blockIdx.x * blockDim.x + threadIdx.x) >> 5;
    int lane = threadIdx.x & 31;
    if (gw >= CB * CT * N) return;
    int n = gw % N;
    int bt = gw / N;
    int b = bt / CT;
    const float* qp = q + (size_t)bt * CH;
    const float* pp = proj + (size_t)(b * N + n) * CH;
    float acc = 0.f;
    for (int k = lane * 4; k < CH; k += 128) {
        float4 qa = *(const float4*)(qp + k);
        float4 pa = *(const float4*)(pp + k);
        acc += qa.x * pa.x + qa.y * pa.y + qa.z * pa.z + qa.w * pa.w;
    }
    #pragma unroll
    for (int o = 16; o; o >>= 1) acc += __shfl_xor_sync(0xffffffffu, acc, o);
    if (lane == 0) out[gw] = acc;
}

// ---------------- fused masked softmaxes + hierarchical combine (bf16 out) ----------------
__global__ __launch_bounds__(256) void combine_kernel(
    const int* __restrict__ s_len, const int* __restrict__ u_len, const int* __restrict__ w_len,
    const int* __restrict__ seg, const int* __restrict__ utt)
{
    int bt = blockIdx.x, b = bt / CT, tid = threadIdx.x;
    __shared__ float ss[CS];
    __shared__ float su[CU];
    __shared__ float sw[CW];
    __shared__ float red[32];
    int sl = s_len[b], ul = u_len[b], wl = w_len[b];

    if (tid < 32) {
        float v = (tid < sl) ? g_sc_s[bt * CS + tid] : -INFINITY;
        float m = v;
        #pragma unroll
        for (int o = 16; o; o >>= 1) m = fmaxf(m, __shfl_xor_sync(0xffffffffu, m, o));
        float e = (tid < sl) ? expf(v - m) : 0.f;
        float s = e;
        #pragma unroll
        for (int o = 16; o; o >>= 1) s += __shfl_xor_sync(0xffffffffu, s, o);
        if (tid < CS) ss[tid] = e / s;
    }
    float uv = (tid < CU && tid < ul) ? g_sc_u[bt * CU + tid] : -INFINITY;
    float um = blockReduceMax256(uv, red);
    float ue = (tid < CU && tid < ul) ? expf(uv - um) : 0.f;
    float us = blockReduceSum256(ue, red);
    if (tid < CU) su[tid] = ue / us;
    float wv[4], we[4];
    float wm = -INFINITY;
    #pragma unroll
    for (int i = 0; i < 4; i++) {
        int idx = tid + 256 * i;
        wv[i] = (idx < wl) ? g_sc_w[(size_t)bt * CW + idx] : -INFINITY;
        wm = fmaxf(wm, wv[i]);
    }
    wm = blockReduceMax256(wm, red);
    float wsum = 0.f;
    #pragma unroll
    for (int i = 0; i < 4; i++) {
        int idx = tid + 256 * i;
        we[i] = (idx < wl) ? expf(wv[i] - wm) : 0.f;
        wsum += we[i];
    }
    wsum = blockReduceSum256(wsum, red);
    #pragma unroll
    for (int i = 0; i < 4; i++) sw[tid + 256 * i] = we[i] / wsum;
    __syncthreads();
    if (tid < CU) {
        float v2 = (tid < ul) ? ss[seg[b * CU + tid]] * su[tid] : 0.f;
        su[tid] = v2;
    }
    __syncthreads();
    float pv[4];
    #pragma unroll
    for (int i = 0; i < 4; i++) {
        int idx = tid + 256 * i;
        pv[i] = (idx < wl) ? su[utt[b * CW + idx]] * sw[idx] : 0.f;
    }
    float pm = fmaxf(fmaxf(pv[0], pv[1]), fmaxf(pv[2], pv[3]));
    pm = blockReduceMax256(pm, red);
    float pe[4];
    float psum = 0.f;
    #pragma unroll
    for (int i = 0; i < 4; i++) { pe[i] = expf(pv[i] - pm); psum += pe[i]; }
    psum = blockReduceSum256(psum, red);
    #pragma unroll
    for (int i = 0; i < 4; i++)
        gb_suw[(size_t)bt * CW + tid + 256 * i] = __float2bfloat16(pe[i] / psum);
}

// ---------------- per-batch transpose of w_output -> bf16 [B,2M,W] ----------------
__global__ void transpose_w_kernel(const float* __restrict__ wo) {
    __shared__ float tile[32][33];
    int b = blockIdx.z;
    int w0 = blockIdx.x * 32, m0 = blockIdx.y * 32;
    int x = threadIdx.x, y = threadIdx.y;
    #pragma unroll
    for (int i = 0; i < 32; i += 8)
        tile[y + i][x] = wo[((size_t)b * CW + (w0 + y + i)) * CM2 + m0 + x];
    __syncthreads();
    #pragma unroll
    for (int i = 0; i < 32; i += 8)
        gb_wT[((size_t)b * CM2 + (m0 + y + i)) * CW + w0 + x] = __float2bfloat16(tile[x][y + i]);
}

// ---------------- in-place log_softmax: single-pass online max+sum ----------------
__global__ __launch_bounds__(256) void logsoftmax_kernel(float* __restrict__ out) {
    __shared__ float redm[8];
    __shared__ float reds[8];
    int row = blockIdx.x, tid = threadIdx.x;
    float* p = out + (size_t)row * CV;
    float m = -INFINITY, s = 0.f;
    for (int i = tid; i < CV; i += 256) {
        float v = p[i];
        if (v > m) { s *= expf(m - v); m = v; }
        s += expf(v - m);
    }
    #pragma unroll
    for (int o = 16; o; o >>= 1) {
        float om = __shfl_xor_sync(0xffffffffu, m, o);
        float os = __shfl_xor_sync(0xffffffffu, s, o);
        float M = fmaxf(m, om);
        s = s * expf(m - M) + os * expf(om - M);
        m = M;
    }
    if ((tid & 31) == 0) { redm[tid >> 5] = m; reds[tid >> 5] = s; }
    __syncthreads();
    if (tid < 32) {
        float mm = (tid < 8) ? redm[tid] : -INFINITY;
        float sv = (tid < 8) ? reds[tid] : 0.f;
        #pragma unroll
        for (int o = 4; o; o >>= 1) {
            float om = __shfl_xor_sync(0xffffffffu, mm, o);
            float os = __shfl_xor_sync(0xffffffffu, sv, o);
            float M = fmaxf(mm, om);
            float e1 = (sv > 0.f) ? sv * expf(mm - M) : 0.f;
            float e2 = (os > 0.f) ? os * expf(om - M) : 0.f;
            sv = e1 + e2;
            mm = M;
        }
        if (tid == 0) { redm[0] = mm; reds[0] = sv; }
    }
    __syncthreads();
    float lse = redm[0] + logf(reds[0]);
    for (int i = tid; i < CV; i += 256) p[i] -= lse;
}

// ---------------- launch ----------------
extern "C" void kernel_launch(void* const* d_in, const int* in_sizes, int n_in,
                              void* d_out, int out_size) {
    const int*   target   = (const int*)d_in[0];
    const float* embedding= (const float*)d_in[1];
    const float* W_ih0    = (const float*)d_in[2];
    const float* W_hh0    = (const float*)d_in[3];
    const float* b_ih0    = (const float*)d_in[4];
    const float* b_hh0    = (const float*)d_in[5];
    const float* W_ih1    = (const float*)d_in[6];
    const float* W_hh1    = (const float*)d_in[7];
    const float* b_ih1    = (const float*)d_in[8];
    const float* b_hh1    = (const float*)d_in[9];
    const float* att_s_w  = (const float*)d_in[10];
    const float* att_s_b  = (const float*)d_in[11];
    const float* att_u_w  = (const float*)d_in[12];
    const float* att_u_b  = (const float*)d_in[13];
    const float* att_w_w  = (const float*)d_in[14];
    const float* att_w_b  = (const float*)d_in[15];
    const float* out_w    = (const float*)d_in[16];
    const float* out_b    = (const float*)d_in[17];
    const float* s_output = (const float*)d_in[18];
    const float* u_output = (const float*)d_in[19];
    const float* w_output = (const float*)d_in[20];
    const int*   s_len    = (const int*)d_in[21];
    const int*   u_len    = (const int*)d_in[22];
    const int*   w_len    = (const int*)d_in[23];
    const int*   seg      = (const int*)d_in[24];
    const int*   utt      = (const int*)d_in[25];
    float* out = (float*)d_out;

    float *p_gi, *p_rnn, *p_ps, *p_pu, *p_scs, *p_scu, *p_scw;
    cudaGetSymbolAddress((void**)&p_gi, g_gi);
    cudaGetSymbolAddress((void**)&p_rnn, g_rnn);
    cudaGetSymbolAddress((void**)&p_ps, g_proj_s);
    cudaGetSymbolAddress((void**)&p_pu, g_proj_u);
    cudaGetSymbolAddress((void**)&p_scs, g_sc_s);
    cudaGetSymbolAddress((void**)&p_scu, g_sc_u);
    cudaGetSymbolAddress((void**)&p_scw, g_sc_w);
    __nv_bfloat16 *b_h1, *b_feat, *b_suw, *b_sout, *b_uout, *b_wout,
                  *b_wT, *b_pw, *b_Wih0, *b_Wih1, *b_atts, *b_attu, *b_attw, *b_outw, *b_emb;
    cudaGetSymbolAddress((void**)&b_emb, gb_emb);
    cudaGetSymbolAddress((void**)&b_h1, gb_h1);
    cudaGetSymbolAddress((void**)&b_feat, gb_feat);
    cudaGetSymbolAddress((void**)&b_suw, gb_suw);
    cudaGetSymbolAddress((void**)&b_sout, gb_sout);
    cudaGetSymbolAddress((void**)&b_uout, gb_uout);
    cudaGetSymbolAddress((void**)&b_wout, gb_wout);
    cudaGetSymbolAddress((void**)&b_wT, gb_wT);
    cudaGetSymbolAddress((void**)&b_pw, gb_pw);
    cudaGetSymbolAddress((void**)&b_Wih0, gb_Wih0);
    cudaGetSymbolAddress((void**)&b_Wih1, gb_Wih1);
    cudaGetSymbolAddress((void**)&b_atts, gb_atts);
    cudaGetSymbolAddress((void**)&b_attu, gb_attu);
    cudaGetSymbolAddress((void**)&b_attw, gb_attw);
    cudaGetSymbolAddress((void**)&b_outw, gb_outw);

    cudaFuncSetAttribute(gru_mma_kernel,
                         cudaFuncAttributeMaxDynamicSharedMemorySize, GRU_SMEM);
    cudaFuncSetAttribute(bgemm_nt<true>,
                         cudaFuncAttributeMaxDynamicSharedMemorySize, BG_DYN);
    cudaFuncSetAttribute(bgemm_nt<false>,
                         cudaFuncAttributeMaxDynamicSharedMemorySize, BG_DYN);

    // 1. merged fp32->bf16 conversions
    convert_all_kernel<<<(unsigned)(SEG8 / 256), 256>>>(
        W_ih0, W_ih1, att_s_w, att_u_w, att_w_w, out_w, s_output, u_output, w_output);
    // 2. embedding gather
    embed_kernel<<<(CB * CT * CE + 255) / 256, 256>>>(target, embedding);
    // 3. gi0 = emb @ W_ih0^T + b_ih0
    bgemm_nt<false><<<dim3((CB * CT) / 128, C3H / 128, 1), 256, BG_DYN>>>(b_emb, b_Wih0, b_ih0, p_gi,
        CE, CE, CE, C3H, 0, 0, 0);
    // 4. GRU layer 0 (tensor-core persistent) -> bf16 gb_h1   [intended ncu capture target]
    gru_mma_kernel<<<GNB, 256, GRU_SMEM>>>(p_gi, W_hh0, b_hh0, nullptr, b_h1, CH);
    // 5. proj_w
    bgemm_nt<true><<<dim3((CB * CW) / 128, CH / 128, 1), 256, BG_DYN>>>(b_wout, b_attw, att_w_b, b_pw,
        CM2, CM2, CM2, CH, 0, 0, 0);
    // 6. gi1 = h1 @ W_ih1^T + b_ih1
    bgemm_nt<false><<<dim3((CB * CT) / 128, C3H / 128, 1), 256, BG_DYN>>>(b_h1, b_Wih1, b_ih1, p_gi,
        CH, CH, CH, C3H, 0, 0, 0);
    // 7. GRU layer 1 -> fp32 rnn + bf16 directly into feat[:, 1024:]
    gru_mma_kernel<<<GNB, 256, GRU_SMEM>>>(p_gi, W_hh1, b_hh1, p_rnn, b_feat + CM2, CF);
    // 8. attention projections s/u
    bgemm_nt<false><<<dim3((CB * CS) / 128, CH / 128, 1), 256, BG_DYN>>>(b_sout, b_atts, att_s_b, p_ps,
        CM, CM, CM, CH, 0, 0, 0);
    bgemm_nt<false><<<dim3((CB * CU) / 128, CH / 128, 1), 256, BG_DYN>>>(b_uout, b_attu, att_u_b, p_pu,
        CM, CM, CM, CH, 0, 0, 0);
    // 9. raw scores
    attn_scores_kernel<<<(CB * CT * CS) / 8, 256>>>(p_rnn, p_ps, p_scs, CS);
    attn_scores_kernel<<<(CB * CT * CU) / 8, 256>>>(p_rnn, p_pu, p_scu, CU);
    bgemm_nt<false><<<dim3(CT / 128, CW / 128, CB), 256, BG_DYN>>>(b_feat + CM2, b_pw, nullptr, p_scw,
        CH, CF, CH, CW, (long)CT * CF, (long)CW * CH, (long)CT * CW);
    // 10. masked softmaxes + hierarchical combine + final softmax
    combine_kernel<<<CB * CT, 256>>>(s_len, u_len, w_len, seg, utt);
    // 11. context = suw @ w_output -> bf16 feat[:, :1024]
    transpose_w_kernel<<<dim3(CW / 32, CM2 / 32, CB), dim3(32, 8)>>>(w_output);
    bgemm_nt<true><<<dim3(CT / 128, CM2 / 128, CB), 256, BG_DYN>>>(b_suw, b_wT, nullptr, b_feat,
        CW, CW, CW, CF, (long)CT * CW, (long)CM2 * CW, (long)CT * CF);
    // 12. logits = feat @ out_w^T + out_b -> d_out (fp32)
    bgemm_nt<false><<<dim3((CB * CT) / 128, CV / 128, 1), 256, BG_DYN>>>(b_feat, b_outw, out_b, out,
        CF, CF, CF, CV, 0, 0, 0);
    // 13. in-place log_softmax (single-pass online)
    logsoftmax_kernel<<<CB * CT, 256>>>(out);
}

// round 15
// speedup vs baseline: 1.1375x; 1.0383x over previous
#include <cuda_runtime.h>
#include <cuda_bf16.h>
#include <math.h>

// ---------------- problem constants ----------------
#define CB 8       // batch
#define CT 128     // time
#define CE 512     // embed dim
#define CH 1024    // hidden
#define CM 512     // mem hidden
#define CM2 1024   // 2*M
#define CS 16
#define CU 128
#define CW 1024
#define CV 32000
#define C3H 3072
#define CF 2048    // H + 2M

// ---------------- fp32 scratch ----------------
__device__ float g_gi[CB * CT * C3H];
__device__ float g_rnn[CB * CT * CH];
__device__ float g_proj_s[CB * CS * CH];
__device__ float g_proj_u[CB * CU * CH];
__device__ float g_sc_s[CB * CT * CS];
__device__ float g_sc_u[CB * CT * CU];
__device__ float g_sc_w[CB * CT * CW];
__device__ unsigned g_bar_arr = 0;
__device__ unsigned g_bar_gen = 0;

// ---------------- bf16 scratch ----------------
__device__ __nv_bfloat16 gb_emb[CB * CT * CE];
__device__ __nv_bfloat16 gb_h1[CB * CT * CH];
__device__ __nv_bfloat16 gb_feat[CB * CT * CF];
__device__ __nv_bfloat16 gb_suw[CB * CT * CW];
__device__ __nv_bfloat16 gb_sout[CB * CS * CM];
__device__ __nv_bfloat16 gb_uout[CB * CU * CM];
__device__ __nv_bfloat16 gb_wout[CB * CW * CM2];
__device__ __nv_bfloat16 gb_wT[CB * CM2 * CW];
__device__ __nv_bfloat16 gb_pw[CB * CW * CH];
__device__ __nv_bfloat16 gb_Wih0[C3H * CE];
__device__ __nv_bfloat16 gb_Wih1[C3H * CH];
__device__ __nv_bfloat16 gb_atts[CH * CM];
__device__ __nv_bfloat16 gb_attu[CH * CM];
__device__ __nv_bfloat16 gb_attw[CH * CM2];
__device__ __nv_bfloat16 gb_outw[(size_t)CV * CF];   // 131 MB
__device__ __nv_bfloat16 g_hbf[2][CB * CH];          // GRU h broadcast (double buffer)

// ---------------- grid barrier (R11 atomic-poll version — proven fastest) ----------------
__device__ __forceinline__ void grid_sync_all(unsigned nb) {
    __threadfence();
    __syncthreads();
    if (threadIdx.x == 0) {
        unsigned gen = atomicAdd(&g_bar_gen, 0u);
        if (atomicAdd(&g_bar_arr, 1u) == nb - 1u) {
            atomicExch(&g_bar_arr, 0u);
            __threadfence();
            atomicAdd(&g_bar_gen, 1u);
        } else {
            while (atomicAdd(&g_bar_gen, 0u) == gen) { __nanosleep(32); }
        }
    }
    __syncthreads();
}

// ---------------- block reductions (256 threads) ----------------
__device__ __forceinline__ float blockReduceMax256(float v, float* red) {
    #pragma unroll
    for (int o = 16; o; o >>= 1) v = fmaxf(v, __shfl_xor_sync(0xffffffffu, v, o));
    if ((threadIdx.x & 31) == 0) red[threadIdx.x >> 5] = v;
    __syncthreads();
    if (threadIdx.x < 32) {
        float r = (threadIdx.x < 8) ? red[threadIdx.x] : -INFINITY;
        #pragma unroll
        for (int o = 4; o; o >>= 1) r = fmaxf(r, __shfl_xor_sync(0xffffffffu, r, o));
        if (threadIdx.x == 0) red[0] = r;
    }
    __syncthreads();
    float out = red[0];
    __syncthreads();
    return out;
}

__device__ __forceinline__ float blockReduceSum256(float v, float* red) {
    #pragma unroll
    for (int o = 16; o; o >>= 1) v += __shfl_xor_sync(0xffffffffu, v, o);
    if ((threadIdx.x & 31) == 0) red[threadIdx.x >> 5] = v;
    __syncthreads();
    if (threadIdx.x < 32) {
        float r = (threadIdx.x < 8) ? red[threadIdx.x] : 0.f;
        #pragma unroll
        for (int o = 4; o; o >>= 1) r += __shfl_xor_sync(0xffffffffu, r, o);
        if (threadIdx.x == 0) red[0] = r;
    }
    __syncthreads();
    float out = red[0];
    __syncthreads();
    return out;
}

// ---------------- single merged fp32->bf16 convert (9 segments) ----------------
#define SEG0 (C3H * CE / 4)
#define SEG1 (SEG0 + C3H * CH / 4)
#define SEG2 (SEG1 + CH * CM / 4)
#define SEG3 (SEG2 + CH * CM / 4)
#define SEG4 (SEG3 + CH * CM2 / 4)
#define SEG5 (SEG4 + (size_t)CV * CF / 4)
#define SEG6 (SEG5 + CB * CS * CM / 4)
#define SEG7 (SEG6 + CB * CU * CM / 4)
#define SEG8 (SEG7 + CB * CW * CM2 / 4)

__global__ void convert_all_kernel(
    const float* __restrict__ s0, const float* __restrict__ s1,
    const float* __restrict__ s2, const float* __restrict__ s3,
    const float* __restrict__ s4, const float* __restrict__ s5,
    const float* __restrict__ s6, const float* __restrict__ s7,
    const float* __restrict__ s8)
{
    size_t i4 = (size_t)blockIdx.x * 256 + threadIdx.x;
    const float* src; __nv_bfloat16* dst; size_t off;
    if      (i4 < SEG0) { src = s0; dst = gb_Wih0; off = i4; }
    else if (i4 < SEG1) { src = s1; dst = gb_Wih1; off = i4 - SEG0; }
    else if (i4 < SEG2) { src = s2; dst = gb_atts; off = i4 - SEG1; }
    else if (i4 < SEG3) { src = s3; dst = gb_attu; off = i4 - SEG2; }
    else if (i4 < SEG4) { src = s4; dst = gb_attw; off = i4 - SEG3; }
    else if (i4 < SEG5) { src = s5; dst = gb_outw; off = i4 - SEG4; }
    else if (i4 < SEG6) { src = s6; dst = gb_sout; off = i4 - SEG5; }
    else if (i4 < SEG7) { src = s7; dst = gb_uout; off = i4 - SEG6; }
    else if (i4 < SEG8) { src = s8; dst = gb_wout; off = i4 - SEG7; }
    else return;
    float4 v = ((const float4*)src)[off];
    __nv_bfloat162* d = (__nv_bfloat162*)(dst + off * 4);
    d[0] = __floats2bfloat162_rn(v.x, v.y);
    d[1] = __floats2bfloat162_rn(v.z, v.w);
}

// ---------------- embedding gather ----------------
__global__ void embed_kernel(const int* __restrict__ target, const float* __restrict__ emb) {
    int i = blockIdx.x * blockDim.x + threadIdx.x;
    if (i < CB * CT * CE) {
        int bt = i / CE, e = i - bt * CE;
        gb_emb[i] = __float2bfloat16(emb[(size_t)target[bt] * CE + e]);
    }
}

// ---------------- mma / ldmatrix / cp.async helpers ----------------
__device__ __forceinline__ void mma_bf16(float* d, const unsigned* a, const unsigned* b) {
    asm volatile(
        "mma.sync.aligned.m16n8k16.row.col.f32.bf16.bf16.f32 "
        "{%0,%1,%2,%3}, {%4,%5,%6,%7}, {%8,%9}, {%0,%1,%2,%3};"
        : "+f"(d[0]), "+f"(d[1]), "+f"(d[2]), "+f"(d[3])
        : "r"(a[0]), "r"(a[1]), "r"(a[2]), "r"(a[3]), "r"(b[0]), "r"(b[1]));
}

__device__ __forceinline__ void ldsm4(unsigned& r0, unsigned& r1, unsigned& r2, unsigned& r3,
                                      unsigned addr) {
    asm volatile("ldmatrix.sync.aligned.m8n8.x4.shared.b16 {%0,%1,%2,%3}, [%4];"
        : "=r"(r0), "=r"(r1), "=r"(r2), "=r"(r3) : "r"(addr));
}

__device__ __forceinline__ void ldsm2(unsigned& r0, unsigned& r1, unsigned addr) {
    asm volatile("ldmatrix.sync.aligned.m8n8.x2.shared.b16 {%0,%1}, [%2];"
        : "=r"(r0), "=r"(r1) : "r"(addr));
}

__device__ __forceinline__ void cpa16(unsigned dst, const void* src) {
    asm volatile("cp.async.ca.shared.global [%0], [%1], 16;" :: "r"(dst), "l"(src));
}

__device__ __forceinline__ unsigned smem_u32(const void* p) {
    unsigned a;
    asm("{ .reg .u64 t; cvta.to.shared.u64 t, %1; cvt.u32.u64 %0, t; }" : "=r"(a) : "l"(p));
    return a;
}

// ---------------- bf16 tensor-core NT GEMM tile (device function) ----------------
// KT=64 stages (canonical SW128: 128B rows, g ^= row&7), 3 stages x 32KB, depth-1
// prefetch, ldmatrix fragments, 8 warps (2M x 4N). Requires K%64==0, K>=128.
#define BG_DYN (3 * 32768)

__device__ __forceinline__ void bgemm_tile(
    const __nv_bfloat16* __restrict__ A, const __nv_bfloat16* __restrict__ Bm,
    const float* __restrict__ bias, void* __restrict__ Cv,
    int K, int lda, int ldb, int ldc, long sA, long sB, long sC,
    int bx, int by, int bz, bool obf16, unsigned baseS)
{
    const __nv_bfloat16* Ab = A + (size_t)bz * sA + (size_t)(bx * 128) * lda;
    const __nv_bfloat16* Bb = Bm + (size_t)bz * sB + (size_t)(by * 128) * ldb;
    int tid = threadIdx.x;
    int warp = tid >> 5, lane = tid & 31;
    int wm = (warp >> 2) * 64, wn = (warp & 3) * 32;
    int lr = lane >> 2, lq = lane & 3;

    int r0 = tid >> 3, g0 = tid & 7;
    unsigned woff0 = (unsigned)(r0 * 128 + ((g0 ^ (r0 & 7)) << 4));
    const __nv_bfloat16* srcA = Ab + (size_t)r0 * lda + g0 * 8;
    const __nv_bfloat16* srcB = Bb + (size_t)r0 * ldb + g0 * 8;

    int lt = lane >> 3, rr = lane & 7;
    int gAoff = lt >> 1;
    unsigned rowA128[4]; unsigned swzA[4];
    #pragma unroll
    for (int mi = 0; mi < 4; mi++) {
        int row = wm + mi * 16 + ((lt & 1) << 3) + rr;
        rowA128[mi] = row * 128;
        swzA[mi] = row & 7;
    }
    int gBoff = lt & 1;
    unsigned rowB128[2]; unsigned swzB[2];
    #pragma unroll
    for (int np = 0; np < 2; np++) {
        int row = wn + np * 16 + ((lt >> 1) << 3) + rr;
        rowB128[np] = row * 128;
        swzB[np] = row & 7;
    }

    float acc[4][4][4];
    #pragma unroll
    for (int mi = 0; mi < 4; mi++)
        #pragma unroll
        for (int ni = 0; ni < 4; ni++)
            #pragma unroll
            for (int r = 0; r < 4; r++) acc[mi][ni][r] = 0.f;

#define STAGE_LOAD(st, kt) do { \
        unsigned sb_ = baseS + (unsigned)(st) * 32768u; \
        _Pragma("unroll") \
        for (int i_ = 0; i_ < 4; i_++) { \
            unsigned o_ = woff0 + (unsigned)i_ * 4096u; \
            size_t ro_ = (size_t)(i_ * 32); \
            cpa16(sb_ + o_, srcA + ro_ * lda + (kt)); \
            cpa16(sb_ + 16384u + o_, srcB + ro_ * ldb + (kt)); \
        } \
        asm volatile("cp.async.commit_group;"); } while (0)

    int nt = K / 64;
    STAGE_LOAD(0, 0);
    STAGE_LOAD(1, 64);

    for (int it = 0; it < nt; it++) {
        if (it + 1 < nt) asm volatile("cp.async.wait_group 1;");
        else             asm volatile("cp.async.wait_group 0;");
        __syncthreads();
        if (it + 2 < nt) {
            int st = (it + 2) % 3, kt = (it + 2) * 64;
            STAGE_LOAD(st, kt);
        }

        unsigned stA = baseS + (unsigned)(it % 3) * 32768u;
        unsigned stB = stA + 16384u;
        #pragma unroll
        for (int ks = 0; ks < 4; ks++) {
            const int kg = ks * 2;
            unsigned a[4][4], b[4][2];
            #pragma unroll
            for (int mi = 0; mi < 4; mi++)
                ldsm4(a[mi][0], a[mi][1], a[mi][2], a[mi][3],
                      stA + rowA128[mi] + ((unsigned)((kg + gAoff) ^ swzA[mi]) << 4));
            #pragma unroll
            for (int np = 0; np < 2; np++)
                ldsm4(b[2 * np][0], b[2 * np][1], b[2 * np + 1][0], b[2 * np + 1][1],
                      stB + rowB128[np] + ((unsigned)((kg + gBoff) ^ swzB[np]) << 4));
            #pragma unroll
            for (int mi = 0; mi < 4; mi++)
                #pragma unroll
                for (int ni = 0; ni < 4; ni++)
                    mma_bf16(acc[mi][ni], a[mi], b[ni]);
        }
    }
#undef STAGE_LOAD

    int m0 = bx * 128, n0 = by * 128;
    #pragma unroll
    for (int mi = 0; mi < 4; mi++) {
        #pragma unroll
        for (int ni = 0; ni < 4; ni++) {
            int m = m0 + wm + mi * 16 + lr;
            int n = n0 + wn + ni * 8 + lq * 2;
            float b0 = bias ? bias[n] : 0.f;
            float b1 = bias ? bias[n + 1] : 0.f;
            float v00 = acc[mi][ni][0] + b0, v01 = acc[mi][ni][1] + b1;
            float v10 = acc[mi][ni][2] + b0, v11 = acc[mi][ni][3] + b1;
            if (obf16) {
                __nv_bfloat16* Cb = (__nv_bfloat16*)Cv + (size_t)bz * sC;
                *(__nv_bfloat162*)(Cb + (size_t)m * ldc + n) = __floats2bfloat162_rn(v00, v01);
                *(__nv_bfloat162*)(Cb + (size_t)(m + 8) * ldc + n) = __floats2bfloat162_rn(v10, v11);
            } else {
                float* Cb = (float*)Cv + (size_t)bz * sC;
                *(float2*)(Cb + (size_t)m * ldc + n) = make_float2(v00, v01);
                *(float2*)(Cb + (size_t)(m + 8) * ldc + n) = make_float2(v10, v11);
            }
        }
    }
}

template<bool OB>
__global__ __launch_bounds__(256, 2) void bgemm_nt(
    const __nv_bfloat16* __restrict__ A, const __nv_bfloat16* __restrict__ Bm,
    const float* __restrict__ bias, void* __restrict__ Cv,
    int K, int lda, int ldb, int ldc, long sA, long sB, long sC)
{
    extern __shared__ unsigned bsm_dyn[];
    bgemm_tile(A, Bm, bias, Cv, K, lda, ldb, ldc, sA, sB, sC,
               blockIdx.x, blockIdx.y, blockIdx.z, OB, smem_u32(bsm_dyn));
}

// ---------------- tensor-core persistent GRU (block body, device fn) ----------------
#define GNB 32
#define GKP 1032
#define GRU_SMEM (104 * GKP * 2 + 2 * 96 * 9 * 4)

__device__ __forceinline__ void gru_block_body(
    int bid, __nv_bfloat16* dyn,
    const float* __restrict__ gi, const float* __restrict__ Wh,
    const float* __restrict__ bh, float* __restrict__ hout,
    __nv_bfloat16* __restrict__ houtb, int ldo)
{
    __nv_bfloat16* whs = dyn;                       // [96][GKP]
    __nv_bfloat16* hs  = dyn + 96 * GKP;            // [8][GKP]
    float* gates = (float*)(dyn + 104 * GKP);       // [96][9]
    float* gis   = gates + 96 * 9;                  // [96][9]
    int tid = threadIdx.x, warp = tid >> 5, lane = tid & 31;
    int j0 = bid * 32;

    for (int idx = tid; idx < 96 * CH; idx += 256) {
        int row = idx >> 10, k = idx & (CH - 1);
        int gate = row >> 5, u = row & 31;
        whs[row * GKP + k] = __float2bfloat16(Wh[(size_t)(gate * CH + j0 + u) * CH + k]);
    }
    for (int idx = tid; idx < CB * GKP; idx += 256) hs[idx] = __float2bfloat16(0.f);

    int j = tid & 31, b = tid >> 5;
    float bhr = bh[j0 + j], bhz = bh[CH + j0 + j], bhn = bh[2 * CH + j0 + j];
    float hprev = 0.f;

    unsigned whb = (unsigned)__cvta_generic_to_shared(whs);
    unsigned hsb = (unsigned)__cvta_generic_to_shared(hs);
    int lt = lane >> 3, rr = lane & 7;
    unsigned aAddr = whb + (unsigned)(((warp << 4) + ((lt & 1) << 3) + rr) * GKP
                                      + ((lt >> 1) << 3)) * 2u;
    int ln = lane & 15;
    unsigned bAddr = hsb + (unsigned)((ln & 7) * GKP + ((ln >> 3) << 3)) * 2u;
    __syncthreads();

    for (int t = 0; t < CT; t++) {
        if (warp < 6) {
            float acc[4][4];
            #pragma unroll
            for (int i = 0; i < 4; i++)
                #pragma unroll
                for (int r = 0; r < 4; r++) acc[i][r] = 0.f;
            #pragma unroll 8
            for (int ks = 0; ks < 64; ks++) {
                unsigned av[4], bv[2];
                ldsm4(av[0], av[1], av[2], av[3], aAddr + ks * 32u);
                ldsm2(bv[0], bv[1], bAddr + ks * 32u);
                mma_bf16(acc[ks & 3], av, bv);
            }
            float c0 = acc[0][0] + acc[1][0] + acc[2][0] + acc[3][0];
            float c1 = acc[0][1] + acc[1][1] + acc[2][1] + acc[3][1];
            float c2 = acc[0][2] + acc[1][2] + acc[2][2] + acc[3][2];
            float c3 = acc[0][3] + acc[1][3] + acc[2][3] + acc[3][3];
            int r_ = lane >> 2, q = lane & 3;
            int rowb = (warp << 4) + r_;
            gates[rowb * 9 + 2 * q]           = c0;
            gates[rowb * 9 + 2 * q + 1]       = c1;
            gates[(rowb + 8) * 9 + 2 * q]     = c2;
            gates[(rowb + 8) * 9 + 2 * q + 1] = c3;
        } else {
            for (int idx = tid - 192; idx < 768; idx += 64) {
                int g = idx >> 8, rem = idx & 255, jj = rem & 31, bb = rem >> 5;
                gis[(g * 32 + jj) * 9 + bb] =
                    gi[(size_t)(bb * CT + t) * C3H + g * CH + j0 + jj];
            }
        }
        __syncthreads();

        float rg = 1.f / (1.f + expf(-(gis[j * 9 + b] + gates[j * 9 + b] + bhr)));
        float zg = 1.f / (1.f + expf(-(gis[(32 + j) * 9 + b] + gates[(32 + j) * 9 + b] + bhz)));
        float ng = tanhf(gis[(64 + j) * 9 + b] + rg * (gates[(64 + j) * 9 + b] + bhn));
        float hn = (1.f - zg) * ng + zg * hprev;
        hprev = hn;
        g_hbf[(t + 1) & 1][b * CH + j0 + j] = __float2bfloat16(hn);
        if (hout) hout[(size_t)(b * CT + t) * CH + j0 + j] = hn;
        houtb[(size_t)(b * CT + t) * ldo + j0 + j] = __float2bfloat16(hn);

        grid_sync_all(GNB);

        const __nv_bfloat16* hb = (const __nv_bfloat16*)g_hbf[(t + 1) & 1];
        for (int idx = tid; idx < CB * CH / 8; idx += 256) {
            int bb = idx >> 7, kk = (idx & 127) << 3;
            *(uint4*)(hs + bb * GKP + kk) = *(const uint4*)(hb + bb * CH + kk);
        }
        __syncthreads();
    }
}

// plain GRU kernel (layer 1)
__global__ __launch_bounds__(256) void gru_mma_kernel(
    const float* __restrict__ gi, const float* __restrict__ Wh,
    const float* __restrict__ bh, float* __restrict__ hout,
    __nv_bfloat16* __restrict__ houtb, int ldo)
{
    extern __shared__ __nv_bfloat16 dyn[];
    gru_block_body(blockIdx.x, dyn, gi, Wh, bh, hout, houtb, ldo);
}

// fused GRU layer-0 + independent attention projections on the idle SMs.
// Blocks [0,32): GRU; [32,544): proj_w (64x8); [544,552): atts (1x8); [552,616): attu (8x8).
__global__ __launch_bounds__(256) void gru_fused_kernel(
    const float* __restrict__ gi, const float* __restrict__ Wh,
    const float* __restrict__ bh, __nv_bfloat16* __restrict__ houtb, int ldo,
    const __nv_bfloat16* __restrict__ wout, const __nv_bfloat16* __restrict__ attw,
    const float* __restrict__ attw_b, __nv_bfloat16* __restrict__ pw,
    const __nv_bfloat16* __restrict__ sout, const __nv_bfloat16* __restrict__ atts,
    const float* __restrict__ atts_b, float* __restrict__ ps,
    const __nv_bfloat16* __restrict__ uout, const __nv_bfloat16* __restrict__ attu,
    const float* __restrict__ attu_b, float* __restrict__ pu)
{
    extern __shared__ __nv_bfloat16 dyn[];
    int bid = blockIdx.x;
    if (bid < GNB) {
        gru_block_body(bid, dyn, gi, Wh, bh, nullptr, houtb, ldo);
    } else if (bid < GNB + 512) {
        int l = bid - GNB;
        bgemm_tile(wout, attw, attw_b, pw, CM2, CM2, CM2, CH, 0, 0, 0,
                   l & 63, l >> 6, 0, true, smem_u32(dyn));
    } else if (bid < GNB + 520) {
        int l = bid - GNB - 512;
        bgemm_tile(sout, atts, atts_b, ps, CM, CM, CM, CH, 0, 0, 0,
                   0, l, 0, false, smem_u32(dyn));
    } else {
        int l = bid - GNB - 520;
        bgemm_tile(uout, attu, attu_b, pu, CM, CM, CM, CH, 0, 0, 0,
                   l & 7, l >> 3, 0, false, smem_u32(dyn));
    }
}

// ---------------- small attention scores (one warp per dot) ----------------
__global__ void attn_scores_kernel(const float* __restrict__ q, const float* __restrict__ proj,
                                   float* __restrict__ out, int N) {
    int gw = (blockIdx.x * blockDim.x + threadIdx.x) >> 5;
    int lane = threadIdx.x & 31;
    if (gw >= CB * CT * N) return;
    int n = gw % N;
    int bt = gw / N;
    int b = bt / CT;
    const float* qp = q + (size_t)bt * CH;
    const float* pp = proj + (size_t)(b * N + n) * CH;
    float acc = 0.f;
    for (int k = lane * 4; k < CH; k += 128) {
        float4 qa = *(const float4*)(qp + k);
        float4 pa = *(const float4*)(pp + k);
        acc += qa.x * pa.x + qa.y * pa.y + qa.z * pa.z + qa.w * pa.w;
    }
    #pragma unroll
    for (int o = 16; o; o >>= 1) acc += __shfl_xor_sync(0xffffffffu, acc, o);
    if (lane == 0) out[gw] = acc;
}

// ---------------- fused masked softmaxes + hierarchical combine (bf16 out) ----------------
__global__ __launch_bounds__(256) void combine_kernel(
    const int* __restrict__ s_len, const int* __restrict__ u_len, const int* __restrict__ w_len,
    const int* __restrict__ seg, const int* __restrict__ utt)
{
    int bt = blockIdx.x, b = bt / CT, tid = threadIdx.x;
    __shared__ float ss[CS];
    __shared__ float su[CU];
    __shared__ float sw[CW];
    __shared__ float red[32];
    int sl = s_len[b], ul = u_len[b], wl = w_len[b];

    if (tid < 32) {
        float v = (tid < sl) ? g_sc_s[bt * CS + tid] : -INFINITY;
        float m = v;
        #pragma unroll
        for (int o = 16; o; o >>= 1) m = fmaxf(m, __shfl_xor_sync(0xffffffffu, m, o));
        float e = (tid < sl) ? expf(v - m) : 0.f;
        float s = e;
        #pragma unroll
        for (int o = 16; o; o >>= 1) s += __shfl_xor_sync(0xffffffffu, s, o);
        if (tid < CS) ss[tid] = e / s;
    }
    float uv = (tid < CU && tid < ul) ? g_sc_u[bt * CU + tid] : -INFINITY;
    float um = blockReduceMax256(uv, red);
    float ue = (tid < CU && tid < ul) ? expf(uv - um) : 0.f;
    float us = blockReduceSum256(ue, red);
    if (tid < CU) su[tid] = ue / us;
    float wv[4], we[4];
    float wm = -INFINITY;
    #pragma unroll
    for (int i = 0; i < 4; i++) {
        int idx = tid + 256 * i;
        wv[i] = (idx < wl) ? g_sc_w[(size_t)bt * CW + idx] : -INFINITY;
        wm = fmaxf(wm, wv[i]);
    }
    wm = blockReduceMax256(wm, red);
    float wsum = 0.f;
    #pragma unroll
    for (int i = 0; i < 4; i++) {
        int idx = tid + 256 * i;
        we[i] = (idx < wl) ? expf(wv[i] - wm) : 0.f;
        wsum += we[i];
    }
    wsum = blockReduceSum256(wsum, red);
    #pragma unroll
    for (int i = 0; i < 4; i++) sw[tid + 256 * i] = we[i] / wsum;
    __syncthreads();
    if (tid < CU) {
        float v2 = (tid < ul) ? ss[seg[b * CU + tid]] * su[tid] : 0.f;
        su[tid] = v2;
    }
    __syncthreads();
    float pv[4];
    #pragma unroll
    for (int i = 0; i < 4; i++) {
        int idx = tid + 256 * i;
        pv[i] = (idx < wl) ? su[utt[b * CW + idx]] * sw[idx] : 0.f;
    }
    float pm = fmaxf(fmaxf(pv[0], pv[1]), fmaxf(pv[2], pv[3]));
    pm = blockReduceMax256(pm, red);
    float pe[4];
    float psum = 0.f;
    #pragma unroll
    for (int i = 0; i < 4; i++) { pe[i] = expf(pv[i] - pm); psum += pe[i]; }
    psum = blockReduceSum256(psum, red);
    #pragma unroll
    for (int i = 0; i < 4; i++)
        gb_suw[(size_t)bt * CW + tid + 256 * i] = __float2bfloat16(pe[i] / psum);
}

// ---------------- per-batch transpose of w_output -> bf16 [B,2M,W] ----------------
__global__ void transpose_w_kernel(const float* __restrict__ wo) {
    __shared__ float tile[32][33];
    int b = blockIdx.z;
    int w0 = blockIdx.x * 32, m0 = blockIdx.y * 32;
    int x = threadIdx.x, y = threadIdx.y;
    #pragma unroll
    for (int i = 0; i < 32; i += 8)
        tile[y + i][x] = wo[((size_t)b * CW + (w0 + y + i)) * CM2 + m0 + x];
    __syncthreads();
    #pragma unroll
    for (int i = 0; i < 32; i += 8)
        gb_wT[((size_t)b * CM2 + (m0 + y + i)) * CW + w0 + x] = __float2bfloat16(tile[x][y + i]);
}

// ---------------- in-place log_softmax: single-pass online max+sum ----------------
__global__ __launch_bounds__(256) void logsoftmax_kernel(float* __restrict__ out) {
    __shared__ float redm[8];
    __shared__ float reds[8];
    int row = blockIdx.x, tid = threadIdx.x;
    float* p = out + (size_t)row * CV;
    float m = -INFINITY, s = 0.f;
    for (int i = tid; i < CV; i += 256) {
        float v = p[i];
        if (v > m) { s *= expf(m - v); m = v; }
        s += expf(v - m);
    }
    #pragma unroll
    for (int o = 16; o; o >>= 1) {
        float om = __shfl_xor_sync(0xffffffffu, m, o);
        float os = __shfl_xor_sync(0xffffffffu, s, o);
        float M = fmaxf(m, om);
        s = s * expf(m - M) + os * expf(om - M);
        m = M;
    }
    if ((tid & 31) == 0) { redm[tid >> 5] = m; reds[tid >> 5] = s; }
    __syncthreads();
    if (tid < 32) {
        float mm = (tid < 8) ? redm[tid] : -INFINITY;
        float sv = (tid < 8) ? reds[tid] : 0.f;
        #pragma unroll
        for (int o = 4; o; o >>= 1) {
            float om = __shfl_xor_sync(0xffffffffu, mm, o);
            float os = __shfl_xor_sync(0xffffffffu, sv, o);
            float M = fmaxf(mm, om);
            float e1 = (sv > 0.f) ? sv * expf(mm - M) : 0.f;
            float e2 = (os > 0.f) ? os * expf(om - M) : 0.f;
            sv = e1 + e2;
            mm = M;
        }
        if (tid == 0) { redm[0] = mm; reds[0] = sv; }
    }
    __syncthreads();
    float lse = redm[0] + logf(reds[0]);
    for (int i = tid; i < CV; i += 256) p[i] -= lse;
}

// ---------------- launch ----------------
extern "C" void kernel_launch(void* const* d_in, const int* in_sizes, int n_in,
                              void* d_out, int out_size) {
    const int*   target   = (const int*)d_in[0];
    const float* embedding= (const float*)d_in[1];
    const float* W_ih0    = (const float*)d_in[2];
    const float* W_hh0    = (const float*)d_in[3];
    const float* b_ih0    = (const float*)d_in[4];
    const float* b_hh0    = (const float*)d_in[5];
    const float* W_ih1    = (const float*)d_in[6];
    const float* W_hh1    = (const float*)d_in[7];
    const float* b_ih1    = (const float*)d_in[8];
    const float* b_hh1    = (const float*)d_in[9];
    const float* att_s_w  = (const float*)d_in[10];
    const float* att_s_b  = (const float*)d_in[11];
    const float* att_u_w  = (const float*)d_in[12];
    const float* att_u_b  = (const float*)d_in[13];
    const float* att_w_w  = (const float*)d_in[14];
    const float* att_w_b  = (const float*)d_in[15];
    const float* out_w    = (const float*)d_in[16];
    const float* out_b    = (const float*)d_in[17];
    const float* s_output = (const float*)d_in[18];
    const float* u_output = (const float*)d_in[19];
    const float* w_output = (const float*)d_in[20];
    const int*   s_len    = (const int*)d_in[21];
    const int*   u_len    = (const int*)d_in[22];
    const int*   w_len    = (const int*)d_in[23];
    const int*   seg      = (const int*)d_in[24];
    const int*   utt      = (const int*)d_in[25];
    float* out = (float*)d_out;

    float *p_gi, *p_rnn, *p_ps, *p_pu, *p_scs, *p_scu, *p_scw;
    cudaGetSymbolAddress((void**)&p_gi, g_gi);
    cudaGetSymbolAddress((void**)&p_rnn, g_rnn);
    cudaGetSymbolAddress((void**)&p_ps, g_proj_s);
    cudaGetSymbolAddress((void**)&p_pu, g_proj_u);
    cudaGetSymbolAddress((void**)&p_scs, g_sc_s);
    cudaGetSymbolAddress((void**)&p_scu, g_sc_u);
    cudaGetSymbolAddress((void**)&p_scw, g_sc_w);
    __nv_bfloat16 *b_h1, *b_feat, *b_suw, *b_sout, *b_uout, *b_wout,
                  *b_wT, *b_pw, *b_Wih0, *b_Wih1, *b_atts, *b_attu, *b_attw, *b_outw, *b_emb;
    cudaGetSymbolAddress((void**)&b_emb, gb_emb);
    cudaGetSymbolAddress((void**)&b_h1, gb_h1);
    cudaGetSymbolAddress((void**)&b_feat, gb_feat);
    cudaGetSymbolAddress((void**)&b_suw, gb_suw);
    cudaGetSymbolAddress((void**)&b_sout, gb_sout);
    cudaGetSymbolAddress((void**)&b_uout, gb_uout);
    cudaGetSymbolAddress((void**)&b_wout, gb_wout);
    cudaGetSymbolAddress((void**)&b_wT, gb_wT);
    cudaGetSymbolAddress((void**)&b_pw, gb_pw);
    cudaGetSymbolAddress((void**)&b_Wih0, gb_Wih0);
    cudaGetSymbolAddress((void**)&b_Wih1, gb_Wih1);
    cudaGetSymbolAddress((void**)&b_atts, gb_atts);
    cudaGetSymbolAddress((void**)&b_attu, gb_attu);
    cudaGetSymbolAddress((void**)&b_attw, gb_attw);
    cudaGetSymbolAddress((void**)&b_outw, gb_outw);

    cudaFuncSetAttribute(gru_mma_kernel,
                         cudaFuncAttributeMaxDynamicSharedMemorySize, GRU_SMEM);
    cudaFuncSetAttribute(gru_fused_kernel,
                         cudaFuncAttributeMaxDynamicSharedMemorySize, GRU_SMEM);
    cudaFuncSetAttribute(bgemm_nt<true>,
                         cudaFuncAttributeMaxDynamicSharedMemorySize, BG_DYN);
    cudaFuncSetAttribute(bgemm_nt<false>,
                         cudaFuncAttributeMaxDynamicSharedMemorySize, BG_DYN);

    // 1. merged fp32->bf16 conversions
    convert_all_kernel<<<(unsigned)(SEG8 / 256), 256>>>(
        W_ih0, W_ih1, att_s_w, att_u_w, att_w_w, out_w, s_output, u_output, w_output);
    // 2. embedding gather
    embed_kernel<<<(CB * CT * CE + 255) / 256, 256>>>(target, embedding);
    // 3. gi0 = emb @ W_ih0^T + b_ih0
    bgemm_nt<false><<<dim3((CB * CT) / 128, C3H / 128, 1), 256, BG_DYN>>>(b_emb, b_Wih0, b_ih0, p_gi,
        CE, CE, CE, C3H, 0, 0, 0);
    // 4. FUSED: GRU layer 0 (blocks 0-31) + proj_w/atts/attu on idle SMs
    gru_fused_kernel<<<GNB + 512 + 8 + 64, 256, GRU_SMEM>>>(
        p_gi, W_hh0, b_hh0, b_h1, CH,
        b_wout, b_attw, att_w_b, b_pw,
        b_sout, b_atts, att_s_b, p_ps,
        b_uout, b_attu, att_u_b, p_pu);
    // 5. gi1 = h1 @ W_ih1^T + b_ih1
    bgemm_nt<false><<<dim3((CB * CT) / 128, C3H / 128, 1), 256, BG_DYN>>>(b_h1, b_Wih1, b_ih1, p_gi,
        CH, CH, CH, C3H, 0, 0, 0);
    // 6. GRU layer 1 -> fp32 rnn + bf16 directly into feat[:, 1024:]   [ncu capture target]
    gru_mma_kernel<<<GNB, 256, GRU_SMEM>>>(p_gi, W_hh1, b_hh1, p_rnn, b_feat + CM2, CF);
    // 7. raw scores
    attn_scores_kernel<<<(CB * CT * CS) / 8, 256>>>(p_rnn, p_ps, p_scs, CS);
    attn_scores_kernel<<<(CB * CT * CU) / 8, 256>>>(p_rnn, p_pu, p_scu, CU);
    bgemm_nt<false><<<dim3(CT / 128, CW / 128, CB), 256, BG_DYN>>>(b_feat + CM2, b_pw, nullptr, p_scw,
        CH, CF, CH, CW, (long)CT * CF, (long)CW * CH, (long)CT * CW);
    // 8. masked softmaxes + hierarchical combine + final softmax
    combine_kernel<<<CB * CT, 256>>>(s_len, u_len, w_len, seg, utt);
    // 9. context = suw @ w_output -> bf16 feat[:, :1024]
    transpose_w_kernel<<<dim3(CW / 32, CM2 / 32, CB), dim3(32, 8)>>>(w_output);
    bgemm_nt<true><<<dim3(CT / 128, CM2 / 128, CB), 256, BG_DYN>>>(b_suw, b_wT, nullptr, b_feat,
        CW, CW, CW, CF, (long)CT * CW, (long)CM2 * CW, (long)CT * CF);
    // 10. logits = feat @ out_w^T + out_b -> d_out (fp32)
    bgemm_nt<false><<<dim3((CB * CT) / 128, CV / 128, 1), 256, BG_DYN>>>(b_feat, b_outw, out_b, out,
        CF, CF, CF, CV, 0, 0, 0);
    // 11. in-place log_softmax (single-pass online)
    logsoftmax_kernel<<<CB * CT, 256>>>(out);
}

// round 16
// speedup vs baseline: 1.4471x; 1.2721x over previous
#include <cuda_runtime.h>
#include <cuda_bf16.h>
#include <math.h>

// ---------------- problem constants ----------------
#define CB 8       // batch
#define CT 128     // time
#define CE 512     // embed dim
#define CH 1024    // hidden
#define CM 512     // mem hidden
#define CM2 1024   // 2*M
#define CS 16
#define CU 128
#define CW 1024
#define CV 32000
#define C3H 3072
#define CF 2048    // H + 2M

// ---------------- fp32 scratch ----------------
__device__ float g_gi[CB * CT * C3H];
__device__ float g_rnn[CB * CT * CH];
__device__ float g_proj_s[CB * CS * CH];
__device__ float g_proj_u[CB * CU * CH];
__device__ float g_sc_s[CB * CT * CS];
__device__ float g_sc_u[CB * CT * CU];
__device__ float g_sc_w[CB * CT * CW];
__device__ unsigned g_bar_arr = 0;
__device__ unsigned g_bar_gen = 0;
__device__ unsigned g_bar1_arr = 0;
__device__ unsigned g_bar1_gen = 0;
__device__ unsigned g_prog0 = 0;

// ---------------- bf16 scratch ----------------
__device__ __nv_bfloat16 gb_emb[CB * CT * CE];
__device__ __nv_bfloat16 gb_feat[CB * CT * CF];
__device__ __nv_bfloat16 gb_suw[CB * CT * CW];
__device__ __nv_bfloat16 gb_sout[CB * CS * CM];
__device__ __nv_bfloat16 gb_uout[CB * CU * CM];
__device__ __nv_bfloat16 gb_wout[CB * CW * CM2];
__device__ __nv_bfloat16 gb_wT[CB * CM2 * CW];
__device__ __nv_bfloat16 gb_pw[CB * CW * CH];
__device__ __nv_bfloat16 gb_Wih0[C3H * CE];
__device__ __nv_bfloat16 gb_atts[CH * CM];
__device__ __nv_bfloat16 gb_attu[CH * CM];
__device__ __nv_bfloat16 gb_attw[CH * CM2];
__device__ __nv_bfloat16 gb_outw[(size_t)CV * CF];   // 131 MB
__device__ __nv_bfloat16 g_hbf[2][CB * CH];          // layer-0 h ring
__device__ __nv_bfloat16 g_hbf1[2 * CB * CH];        // layer-1 h ring
__device__ __nv_bfloat16 g_h1s[(size_t)CT * CB * CH];// all layer-0 outputs [t][b][1024]

// ---------------- grid barrier (parametrized; R11-proven atomic-poll) ----------------
__device__ __forceinline__ void grid_sync_all(unsigned nb, unsigned* arr, unsigned* gen) {
    __threadfence();
    __syncthreads();
    if (threadIdx.x == 0) {
        unsigned g = atomicAdd(gen, 0u);
        if (atomicAdd(arr, 1u) == nb - 1u) {
            atomicExch(arr, 0u);
            __threadfence();
            atomicAdd(gen, 1u);
        } else {
            while (atomicAdd(gen, 0u) == g) { __nanosleep(32); }
        }
    }
    __syncthreads();
}

// ---------------- block reductions (256 threads) ----------------
__device__ __forceinline__ float blockReduceMax256(float v, float* red) {
    #pragma unroll
    for (int o = 16; o; o >>= 1) v = fmaxf(v, __shfl_xor_sync(0xffffffffu, v, o));
    if ((threadIdx.x & 31) == 0) red[threadIdx.x >> 5] = v;
    __syncthreads();
    if (threadIdx.x < 32) {
        float r = (threadIdx.x < 8) ? red[threadIdx.x] : -INFINITY;
        #pragma unroll
        for (int o = 4; o; o >>= 1) r = fmaxf(r, __shfl_xor_sync(0xffffffffu, r, o));
        if (threadIdx.x == 0) red[0] = r;
    }
    __syncthreads();
    float out = red[0];
    __syncthreads();
    return out;
}

__device__ __forceinline__ float blockReduceSum256(float v, float* red) {
    #pragma unroll
    for (int o = 16; o; o >>= 1) v += __shfl_xor_sync(0xffffffffu, v, o);
    if ((threadIdx.x & 31) == 0) red[threadIdx.x >> 5] = v;
    __syncthreads();
    if (threadIdx.x < 32) {
        float r = (threadIdx.x < 8) ? red[threadIdx.x] : 0.f;
        #pragma unroll
        for (int o = 4; o; o >>= 1) r += __shfl_xor_sync(0xffffffffu, r, o);
        if (threadIdx.x == 0) red[0] = r;
    }
    __syncthreads();
    float out = red[0];
    __syncthreads();
    return out;
}

// ---------------- single merged fp32->bf16 convert (8 segments; Wih1 no longer needed) ----
#define SEG0 (C3H * CE / 4)
#define SEG1 (SEG0 + CH * CM / 4)
#define SEG2 (SEG1 + CH * CM / 4)
#define SEG3 (SEG2 + CH * CM2 / 4)
#define SEG4 (SEG3 + (size_t)CV * CF / 4)
#define SEG5 (SEG4 + CB * CS * CM / 4)
#define SEG6 (SEG5 + CB * CU * CM / 4)
#define SEG7 (SEG6 + CB * CW * CM2 / 4)

__global__ void convert_all_kernel(
    const float* __restrict__ s0, const float* __restrict__ s1,
    const float* __restrict__ s2, const float* __restrict__ s3,
    const float* __restrict__ s4, const float* __restrict__ s5,
    const float* __restrict__ s6, const float* __restrict__ s7)
{
    size_t i4 = (size_t)blockIdx.x * 256 + threadIdx.x;
    const float* src; __nv_bfloat16* dst; size_t off;
    if      (i4 < SEG0) { src = s0; dst = gb_Wih0; off = i4; }
    else if (i4 < SEG1) { src = s1; dst = gb_atts; off = i4 - SEG0; }
    else if (i4 < SEG2) { src = s2; dst = gb_attu; off = i4 - SEG1; }
    else if (i4 < SEG3) { src = s3; dst = gb_attw; off = i4 - SEG2; }
    else if (i4 < SEG4) { src = s4; dst = gb_outw; off = i4 - SEG3; }
    else if (i4 < SEG5) { src = s5; dst = gb_sout; off = i4 - SEG4; }
    else if (i4 < SEG6) { src = s6; dst = gb_uout; off = i4 - SEG5; }
    else if (i4 < SEG7) { src = s7; dst = gb_wout; off = i4 - SEG6; }
    else return;
    float4 v = ((const float4*)src)[off];
    __nv_bfloat162* d = (__nv_bfloat162*)(dst + off * 4);
    d[0] = __floats2bfloat162_rn(v.x, v.y);
    d[1] = __floats2bfloat162_rn(v.z, v.w);
}

// ---------------- embedding gather ----------------
__global__ void embed_kernel(const int* __restrict__ target, const float* __restrict__ emb) {
    int i = blockIdx.x * blockDim.x + threadIdx.x;
    if (i < CB * CT * CE) {
        int bt = i / CE, e = i - bt * CE;
        gb_emb[i] = __float2bfloat16(emb[(size_t)target[bt] * CE + e]);
    }
}

// ---------------- mma / ldmatrix / cp.async helpers ----------------
__device__ __forceinline__ void mma_bf16(float* d, const unsigned* a, const unsigned* b) {
    asm volatile(
        "mma.sync.aligned.m16n8k16.row.col.f32.bf16.bf16.f32 "
        "{%0,%1,%2,%3}, {%4,%5,%6,%7}, {%8,%9}, {%0,%1,%2,%3};"
        : "+f"(d[0]), "+f"(d[1]), "+f"(d[2]), "+f"(d[3])
        : "r"(a[0]), "r"(a[1]), "r"(a[2]), "r"(a[3]), "r"(b[0]), "r"(b[1]));
}

__device__ __forceinline__ void ldsm4(unsigned& r0, unsigned& r1, unsigned& r2, unsigned& r3,
                                      unsigned addr) {
    asm volatile("ldmatrix.sync.aligned.m8n8.x4.shared.b16 {%0,%1,%2,%3}, [%4];"
        : "=r"(r0), "=r"(r1), "=r"(r2), "=r"(r3) : "r"(addr));
}

__device__ __forceinline__ void ldsm2(unsigned& r0, unsigned& r1, unsigned addr) {
    asm volatile("ldmatrix.sync.aligned.m8n8.x2.shared.b16 {%0,%1}, [%2];"
        : "=r"(r0), "=r"(r1) : "r"(addr));
}

__device__ __forceinline__ void cpa16(unsigned dst, const void* src) {
    asm volatile("cp.async.ca.shared.global [%0], [%1], 16;" :: "r"(dst), "l"(src));
}

__device__ __forceinline__ unsigned smem_u32(const void* p) {
    unsigned a;
    asm("{ .reg .u64 t; cvta.to.shared.u64 t, %1; cvt.u32.u64 %0, t; }" : "=r"(a) : "l"(p));
    return a;
}

// ---------------- bf16 tensor-core NT GEMM tile (device function) ----------------
#define BG_DYN (3 * 32768)

__device__ __forceinline__ void bgemm_tile(
    const __nv_bfloat16* __restrict__ A, const __nv_bfloat16* __restrict__ Bm,
    const float* __restrict__ bias, void* __restrict__ Cv,
    int K, int lda, int ldb, int ldc, long sA, long sB, long sC,
    int bx, int by, int bz, bool obf16, unsigned baseS)
{
    const __nv_bfloat16* Ab = A + (size_t)bz * sA + (size_t)(bx * 128) * lda;
    const __nv_bfloat16* Bb = Bm + (size_t)bz * sB + (size_t)(by * 128) * ldb;
    int tid = threadIdx.x;
    int warp = tid >> 5, lane = tid & 31;
    int wm = (warp >> 2) * 64, wn = (warp & 3) * 32;
    int lr = lane >> 2, lq = lane & 3;

    int r0 = tid >> 3, g0 = tid & 7;
    unsigned woff0 = (unsigned)(r0 * 128 + ((g0 ^ (r0 & 7)) << 4));
    const __nv_bfloat16* srcA = Ab + (size_t)r0 * lda + g0 * 8;
    const __nv_bfloat16* srcB = Bb + (size_t)r0 * ldb + g0 * 8;

    int lt = lane >> 3, rr = lane & 7;
    int gAoff = lt >> 1;
    unsigned rowA128[4]; unsigned swzA[4];
    #pragma unroll
    for (int mi = 0; mi < 4; mi++) {
        int row = wm + mi * 16 + ((lt & 1) << 3) + rr;
        rowA128[mi] = row * 128;
        swzA[mi] = row & 7;
    }
    int gBoff = lt & 1;
    unsigned rowB128[2]; unsigned swzB[2];
    #pragma unroll
    for (int np = 0; np < 2; np++) {
        int row = wn + np * 16 + ((lt >> 1) << 3) + rr;
        rowB128[np] = row * 128;
        swzB[np] = row & 7;
    }

    float acc[4][4][4];
    #pragma unroll
    for (int mi = 0; mi < 4; mi++)
        #pragma unroll
        for (int ni = 0; ni < 4; ni++)
            #pragma unroll
            for (int r = 0; r < 4; r++) acc[mi][ni][r] = 0.f;

#define STAGE_LOAD(st, kt) do { \
        unsigned sb_ = baseS + (unsigned)(st) * 32768u; \
        _Pragma("unroll") \
        for (int i_ = 0; i_ < 4; i_++) { \
            unsigned o_ = woff0 + (unsigned)i_ * 4096u; \
            size_t ro_ = (size_t)(i_ * 32); \
            cpa16(sb_ + o_, srcA + ro_ * lda + (kt)); \
            cpa16(sb_ + 16384u + o_, srcB + ro_ * ldb + (kt)); \
        } \
        asm volatile("cp.async.commit_group;"); } while (0)

    int nt = K / 64;
    STAGE_LOAD(0, 0);
    STAGE_LOAD(1, 64);

    for (int it = 0; it < nt; it++) {
        if (it + 1 < nt) asm volatile("cp.async.wait_group 1;");
        else             asm volatile("cp.async.wait_group 0;");
        __syncthreads();
        if (it + 2 < nt) {
            int st = (it + 2) % 3, kt = (it + 2) * 64;
            STAGE_LOAD(st, kt);
        }

        unsigned stA = baseS + (unsigned)(it % 3) * 32768u;
        unsigned stB = stA + 16384u;
        #pragma unroll
        for (int ks = 0; ks < 4; ks++) {
            const int kg = ks * 2;
            unsigned a[4][4], b[4][2];
            #pragma unroll
            for (int mi = 0; mi < 4; mi++)
                ldsm4(a[mi][0], a[mi][1], a[mi][2], a[mi][3],
                      stA + rowA128[mi] + ((unsigned)((kg + gAoff) ^ swzA[mi]) << 4));
            #pragma unroll
            for (int np = 0; np < 2; np++)
                ldsm4(b[2 * np][0], b[2 * np][1], b[2 * np + 1][0], b[2 * np + 1][1],
                      stB + rowB128[np] + ((unsigned)((kg + gBoff) ^ swzB[np]) << 4));
            #pragma unroll
            for (int mi = 0; mi < 4; mi++)
                #pragma unroll
                for (int ni = 0; ni < 4; ni++)
                    mma_bf16(acc[mi][ni], a[mi], b[ni]);
        }
    }
#undef STAGE_LOAD

    int m0 = bx * 128, n0 = by * 128;
    #pragma unroll
    for (int mi = 0; mi < 4; mi++) {
        #pragma unroll
        for (int ni = 0; ni < 4; ni++) {
            int m = m0 + wm + mi * 16 + lr;
            int n = n0 + wn + ni * 8 + lq * 2;
            float b0 = bias ? bias[n] : 0.f;
            float b1 = bias ? bias[n + 1] : 0.f;
            float v00 = acc[mi][ni][0] + b0, v01 = acc[mi][ni][1] + b1;
            float v10 = acc[mi][ni][2] + b0, v11 = acc[mi][ni][3] + b1;
            if (obf16) {
                __nv_bfloat16* Cb = (__nv_bfloat16*)Cv + (size_t)bz * sC;
                *(__nv_bfloat162*)(Cb + (size_t)m * ldc + n) = __floats2bfloat162_rn(v00, v01);
                *(__nv_bfloat162*)(Cb + (size_t)(m + 8) * ldc + n) = __floats2bfloat162_rn(v10, v11);
            } else {
                float* Cb = (float*)Cv + (size_t)bz * sC;
                *(float2*)(Cb + (size_t)m * ldc + n) = make_float2(v00, v01);
                *(float2*)(Cb + (size_t)(m + 8) * ldc + n) = make_float2(v10, v11);
            }
        }
    }
}

template<bool OB>
__global__ __launch_bounds__(256, 2) void bgemm_nt(
    const __nv_bfloat16* __restrict__ A, const __nv_bfloat16* __restrict__ Bm,
    const float* __restrict__ bias, void* __restrict__ Cv,
    int K, int lda, int ldb, int ldc, long sA, long sB, long sC)
{
    extern __shared__ unsigned bsm_dyn[];
    bgemm_tile(A, Bm, bias, Cv, K, lda, ldb, ldc, sA, sB, sC,
               blockIdx.x, blockIdx.y, blockIdx.z, OB, smem_u32(bsm_dyn));
}

// ---------------- layer-0 GRU block body (32 blocks x 32 units) ----------------
#define GNB0 32
#define GNB1 64
#define GKP 1032
#define GRU_SMEM (104 * GKP * 2 + 2 * 96 * 9 * 4)   // 221,568 B (layer-1 uses 221,056)

__device__ __forceinline__ void gru0_body(
    int bid, __nv_bfloat16* dyn,
    const float* __restrict__ gi, const float* __restrict__ Wh,
    const float* __restrict__ bh)
{
    __nv_bfloat16* whs = dyn;                       // [96][GKP]
    __nv_bfloat16* hs  = dyn + 96 * GKP;            // [8][GKP]
    float* gates = (float*)(dyn + 104 * GKP);       // [96][9]
    float* gis   = gates + 96 * 9;                  // [96][9]
    int tid = threadIdx.x, warp = tid >> 5, lane = tid & 31;
    int j0 = bid * 32;

    for (int idx = tid; idx < 96 * CH; idx += 256) {
        int row = idx >> 10, k = idx & (CH - 1);
        int gate = row >> 5, u = row & 31;
        whs[row * GKP + k] = __float2bfloat16(Wh[(size_t)(gate * CH + j0 + u) * CH + k]);
    }
    for (int idx = tid; idx < CB * GKP; idx += 256) hs[idx] = __float2bfloat16(0.f);

    int j = tid & 31, b = tid >> 5;
    float bhr = bh[j0 + j], bhz = bh[CH + j0 + j], bhn = bh[2 * CH + j0 + j];
    float hprev = 0.f;

    unsigned whb = (unsigned)__cvta_generic_to_shared(whs);
    unsigned hsb = (unsigned)__cvta_generic_to_shared(hs);
    int lt = lane >> 3, rr = lane & 7;
    unsigned aAddr = whb + (unsigned)(((warp << 4) + ((lt & 1) << 3) + rr) * GKP
                                      + ((lt >> 1) << 3)) * 2u;
    int ln = lane & 15;
    unsigned bAddr = hsb + (unsigned)((ln & 7) * GKP + ((ln >> 3) << 3)) * 2u;
    __syncthreads();

    for (int t = 0; t < CT; t++) {
        if (warp < 6) {
            float acc[4][4];
            #pragma unroll
            for (int i = 0; i < 4; i++)
                #pragma unroll
                for (int r = 0; r < 4; r++) acc[i][r] = 0.f;
            #pragma unroll 8
            for (int ks = 0; ks < 64; ks++) {
                unsigned av[4], bv[2];
                ldsm4(av[0], av[1], av[2], av[3], aAddr + ks * 32u);
                ldsm2(bv[0], bv[1], bAddr + ks * 32u);
                mma_bf16(acc[ks & 3], av, bv);
            }
            float c0 = acc[0][0] + acc[1][0] + acc[2][0] + acc[3][0];
            float c1 = acc[0][1] + acc[1][1] + acc[2][1] + acc[3][1];
            float c2 = acc[0][2] + acc[1][2] + acc[2][2] + acc[3][2];
            float c3 = acc[0][3] + acc[1][3] + acc[2][3] + acc[3][3];
            int r_ = lane >> 2, q = lane & 3;
            int rowb = (warp << 4) + r_;
            gates[rowb * 9 + 2 * q]           = c0;
            gates[rowb * 9 + 2 * q + 1]       = c1;
            gates[(rowb + 8) * 9 + 2 * q]     = c2;
            gates[(rowb + 8) * 9 + 2 * q + 1] = c3;
        } else {
            for (int idx = tid - 192; idx < 768; idx += 64) {
                int g = idx >> 8, rem = idx & 255, jj = rem & 31, bb = rem >> 5;
                gis[(g * 32 + jj) * 9 + bb] =
                    gi[(size_t)(bb * CT + t) * C3H + g * CH + j0 + jj];
            }
        }
        __syncthreads();

        float rg = 1.f / (1.f + expf(-(gis[j * 9 + b] + gates[j * 9 + b] + bhr)));
        float zg = 1.f / (1.f + expf(-(gis[(32 + j) * 9 + b] + gates[(32 + j) * 9 + b] + bhz)));
        float ng = tanhf(gis[(64 + j) * 9 + b] + rg * (gates[(64 + j) * 9 + b] + bhn));
        float hn = (1.f - zg) * ng + zg * hprev;
        hprev = hn;
        __nv_bfloat16 hb16 = __float2bfloat16(hn);
        g_hbf[(t + 1) & 1][b * CH + j0 + j] = hb16;
        g_h1s[(size_t)t * (CB * CH) + b * CH + j0 + j] = hb16;

        grid_sync_all(GNB0, &g_bar_arr, &g_bar_gen);
        if (bid == 0 && tid == 0) atomicAdd(&g_prog0, 1u);   // h1[t] published

        const __nv_bfloat16* hb = (const __nv_bfloat16*)g_hbf[(t + 1) & 1];
        for (int idx = tid; idx < CB * CH / 8; idx += 256) {
            int bb = idx >> 7, kk = (idx & 127) << 3;
            *(uint4*)(hs + bb * GKP + kk) = *(const uint4*)(hb + bb * CH + kk);
        }
        __syncthreads();
    }
}

// ---------------- layer-1 GRU block body (64 blocks x 16 units, inline gi1) ------------
// smem (bf16 elems): rzw [32][RZP] (r/z rows: cols 0..1023 = Wih1, 1024..2047 = Whh1),
// nih [16][1032], nhh [16][1032], hbuf [8][1032]; gbuf float[4][48][9] after.
#define RZP 2056
#define L1_NIH (32 * RZP)            // 65792
#define L1_NHH (L1_NIH + 16 * 1032)  // 82304
#define L1_HB  (L1_NHH + 16 * 1032)  // 98816

__device__ __forceinline__ void gru1_body(
    int bid1, __nv_bfloat16* dyn,
    const float* __restrict__ Wih, const float* __restrict__ Whh,
    const float* __restrict__ bih, const float* __restrict__ bhh,
    float* __restrict__ rnn_out, __nv_bfloat16* __restrict__ featb)
{
    __nv_bfloat16* rzw = dyn;
    __nv_bfloat16* nih = dyn + L1_NIH;
    __nv_bfloat16* nhh = dyn + L1_NHH;
    __nv_bfloat16* hb  = dyn + L1_HB;
    float* gbuf = (float*)(dyn + L1_HB + 8 * 1032);
    int tid = threadIdx.x, warp = tid >> 5, lane = tid & 31;
    int j0 = bid1 * 16;

    // load fused weights
    for (int idx = tid; idx < 32 * 2048; idx += 256) {
        int row = idx >> 11, k = idx & 2047;
        int gate = row >> 4, u = row & 15;
        float v = (k < 1024) ? Wih[(size_t)(gate * CH + j0 + u) * CH + k]
                             : Whh[(size_t)(gate * CH + j0 + u) * CH + (k - 1024)];
        rzw[row * RZP + k] = __float2bfloat16(v);
    }
    for (int idx = tid; idx < 16 * 1024; idx += 256) {
        int row = idx >> 10, k = idx & 1023;
        nih[row * 1032 + k] = __float2bfloat16(Wih[(size_t)(2 * CH + j0 + row) * CH + k]);
        nhh[row * 1032 + k] = __float2bfloat16(Whh[(size_t)(2 * CH + j0 + row) * CH + k]);
    }
    // cooperative zero of hl1 ring (both parities)
    for (int idx = tid + bid1 * 256; idx < 2 * CB * CH; idx += GNB1 * 256)
        g_hbf1[idx] = __float2bfloat16(0.f);

    int u = tid & 15, b = tid >> 4;   // valid for tid < 128
    float bihr = 0, bihz = 0, bihn = 0, bhhr = 0, bhhz = 0, bhhn = 0;
    if (tid < 128) {
        bihr = bih[j0 + u]; bihz = bih[CH + j0 + u]; bihn = bih[2 * CH + j0 + u];
        bhhr = bhh[j0 + u]; bhhz = bhh[CH + j0 + u]; bhhn = bhh[2 * CH + j0 + u];
    }
    float hprev = 0.f;

    // MMA geometry: warp -> (tau = row tile, kh = K half of the pass's 1024)
    int tau = warp >> 1, kh = warp & 1;
    int lt = lane >> 3, rr = lane & 7;
    int rowIn = ((lt & 1) << 3) + rr;
    unsigned base = (unsigned)__cvta_generic_to_shared(dyn);
    unsigned aByte0, aByte1;
    if (tau < 2) {
        unsigned e0 = (unsigned)((tau * 16 + rowIn) * RZP + ((lt >> 1) << 3) + kh * 512);
        aByte0 = base + e0 * 2u;
        aByte1 = base + (e0 + 1024u) * 2u;
    } else {
        unsigned eo = (unsigned)(rowIn * 1032 + ((lt >> 1) << 3) + kh * 512);
        aByte0 = base + ((unsigned)L1_NIH + eo) * 2u;
        aByte1 = base + ((unsigned)L1_NHH + eo) * 2u;
    }
    int ln = lane & 15;
    unsigned bByte = base + (unsigned)(L1_HB + (ln & 7) * 1032 + ((ln >> 3) << 3) + kh * 512) * 2u;

    grid_sync_all(GNB1, &g_bar1_arr, &g_bar1_gen);   // ring zero visible to all

#define L1_MMA(PASS, AADDR) do { \
        float acc[4][4]; \
        _Pragma("unroll") \
        for (int i_ = 0; i_ < 4; i_++) \
            _Pragma("unroll") \
            for (int r_2 = 0; r_2 < 4; r_2++) acc[i_][r_2] = 0.f; \
        _Pragma("unroll 8") \
        for (int ks = 0; ks < 32; ks++) { \
            unsigned av[4], bv[2]; \
            ldsm4(av[0], av[1], av[2], av[3], (AADDR) + ks * 32u); \
            ldsm2(bv[0], bv[1], bByte + ks * 32u); \
            mma_bf16(acc[ks & 3], av, bv); \
        } \
        float c0 = acc[0][0] + acc[1][0] + acc[2][0] + acc[3][0]; \
        float c1 = acc[0][1] + acc[1][1] + acc[2][1] + acc[3][1]; \
        float c2 = acc[0][2] + acc[1][2] + acc[2][2] + acc[3][2]; \
        float c3 = acc[0][3] + acc[1][3] + acc[2][3] + acc[3][3]; \
        int r_ = lane >> 2, q = lane & 3; \
        int rowb = tau * 16 + r_; \
        float* gs = gbuf + ((PASS) * 2 + kh) * 48 * 9; \
        gs[rowb * 9 + 2 * q]           = c0; \
        gs[rowb * 9 + 2 * q + 1]       = c1; \
        gs[(rowb + 8) * 9 + 2 * q]     = c2; \
        gs[(rowb + 8) * 9 + 2 * q + 1] = c3; } while (0)

    for (int t = 0; t < CT; t++) {
        if (tid == 0) {
            while (atomicAdd(&g_prog0, 0u) <= (unsigned)t) { __nanosleep(32); }
            __threadfence();
        }
        __syncthreads();
        // hb = h1[t]
        {
            const __nv_bfloat16* src = g_h1s + (size_t)t * (CB * CH);
            for (int idx = tid; idx < CB * CH / 8; idx += 256) {
                int bb = idx >> 7, kk = (idx & 127) << 3;
                *(uint4*)(hb + bb * 1032 + kk) = *(const uint4*)(src + bb * CH + kk);
            }
        }
        __syncthreads();
        if (warp < 6) L1_MMA(0, aByte0);
        __syncthreads();
        // hb = hl1[t-1]
        {
            const __nv_bfloat16* src = g_hbf1 + ((t + 1) & 1) * (CB * CH);
            for (int idx = tid; idx < CB * CH / 8; idx += 256) {
                int bb = idx >> 7, kk = (idx & 127) << 3;
                *(uint4*)(hb + bb * 1032 + kk) = *(const uint4*)(src + bb * CH + kk);
            }
        }
        __syncthreads();
        if (warp < 6) L1_MMA(1, aByte1);
        __syncthreads();

        if (tid < 128) {
            #define GG(s, r) gbuf[(s) * 432 + (r) * 9 + b]
            float rp = GG(0, u) + GG(1, u) + GG(2, u) + GG(3, u) + bihr + bhhr;
            float zp = GG(0, 16 + u) + GG(1, 16 + u) + GG(2, 16 + u) + GG(3, 16 + u) + bihz + bhhz;
            float inn = GG(0, 32 + u) + GG(1, 32 + u) + bihn;
            float hnn = GG(2, 32 + u) + GG(3, 32 + u) + bhhn;
            #undef GG
            float rg = 1.f / (1.f + expf(-rp));
            float zg = 1.f / (1.f + expf(-zp));
            float ng = tanhf(inn + rg * hnn);
            float hn = (1.f - zg) * ng + zg * hprev;
            hprev = hn;
            g_hbf1[(t & 1) * (CB * CH) + b * CH + j0 + u] = __float2bfloat16(hn);
            rnn_out[(size_t)(b * CT + t) * CH + j0 + u] = hn;
            featb[(size_t)(b * CT + t) * CF + CM2 + j0 + u] = __float2bfloat16(hn);
        }
        grid_sync_all(GNB1, &g_bar1_arr, &g_bar1_gen);
    }
#undef L1_MMA
    grid_sync_all(GNB1, &g_bar1_arr, &g_bar1_gen);
    if (bid1 == 0 && tid == 0) atomicExch(&g_prog0, 0u);     // replay-safe reset
}

// ---------------- mega kernel: pipelined 2-layer GRU + attn projections --------------
__global__ __launch_bounds__(256) void mega_kernel(
    const float* __restrict__ gi, const float* __restrict__ Wh0, const float* __restrict__ bh0,
    const float* __restrict__ Wih1, const float* __restrict__ Whh1,
    const float* __restrict__ bih1, const float* __restrict__ bhh1,
    float* __restrict__ rnn_out, __nv_bfloat16* __restrict__ featb,
    const __nv_bfloat16* __restrict__ wout, const __nv_bfloat16* __restrict__ attw,
    const float* __restrict__ attw_b, __nv_bfloat16* __restrict__ pw,
    const __nv_bfloat16* __restrict__ sout, const __nv_bfloat16* __restrict__ atts,
    const float* __restrict__ atts_b, float* __restrict__ ps,
    const __nv_bfloat16* __restrict__ uout, const __nv_bfloat16* __restrict__ attu,
    const float* __restrict__ attu_b, float* __restrict__ pu)
{
    extern __shared__ __nv_bfloat16 dyn[];
    int bid = blockIdx.x;
    if (bid < GNB0) {
        gru0_body(bid, dyn, gi, Wh0, bh0);
    } else if (bid < GNB0 + GNB1) {
        gru1_body(bid - GNB0, dyn, Wih1, Whh1, bih1, bhh1, rnn_out, featb);
    } else if (bid < GNB0 + GNB1 + 512) {
        int l = bid - GNB0 - GNB1;
        bgemm_tile(wout, attw, attw_b, pw, CM2, CM2, CM2, CH, 0, 0, 0,
                   l & 63, l >> 6, 0, true, smem_u32(dyn));
    } else if (bid < GNB0 + GNB1 + 520) {
        int l = bid - GNB0 - GNB1 - 512;
        bgemm_tile(sout, atts, atts_b, ps, CM, CM, CM, CH, 0, 0, 0,
                   0, l, 0, false, smem_u32(dyn));
    } else {
        int l = bid - GNB0 - GNB1 - 520;
        bgemm_tile(uout, attu, attu_b, pu, CM, CM, CM, CH, 0, 0, 0,
                   l & 7, l >> 3, 0, false, smem_u32(dyn));
    }
}

// ---------------- small attention scores (one warp per dot) ----------------
__global__ void attn_scores_kernel(const float* __restrict__ q, const float* __restrict__ proj,
                                   float* __restrict__ out, int N) {
    int gw = (blockIdx.x * blockDim.x + threadIdx.x) >> 5;
    int lane = threadIdx.x & 31;
    if (gw >= CB * CT * N) return;
    int n = gw % N;
    int bt = gw / N;
    int b = bt / CT;
    const float* qp = q + (size_t)bt * CH;
    const float* pp = proj + (size_t)(b * N + n) * CH;
    float acc = 0.f;
    for (int k = lane * 4; k < CH; k += 128) {
        float4 qa = *(const float4*)(qp + k);
        float4 pa = *(const float4*)(pp + k);
        acc += qa.x * pa.x + qa.y * pa.y + qa.z * pa.z + qa.w * pa.w;
    }
    #pragma unroll
    for (int o = 16; o; o >>= 1) acc += __shfl_xor_sync(0xffffffffu, acc, o);
    if (lane == 0) out[gw] = acc;
}

// ---------------- fused masked softmaxes + hierarchical combine (bf16 out) ----------------
__global__ __launch_bounds__(256) void combine_kernel(
    const int* __restrict__ s_len, const int* __restrict__ u_len, const int* __restrict__ w_len,
    const int* __restrict__ seg, const int* __restrict__ utt)
{
    int bt = blockIdx.x, b = bt / CT, tid = threadIdx.x;
    __shared__ float ss[CS];
    __shared__ float su[CU];
    __shared__ float sw[CW];
    __shared__ float red[32];
    int sl = s_len[b], ul = u_len[b], wl = w_len[b];

    if (tid < 32) {
        float v = (tid < sl) ? g_sc_s[bt * CS + tid] : -INFINITY;
        float m = v;
        #pragma unroll
        for (int o = 16; o; o >>= 1) m = fmaxf(m, __shfl_xor_sync(0xffffffffu, m, o));
        float e = (tid < sl) ? expf(v - m) : 0.f;
        float s = e;
        #pragma unroll
        for (int o = 16; o; o >>= 1) s += __shfl_xor_sync(0xffffffffu, s, o);
        if (tid < CS) ss[tid] = e / s;
    }
    float uv = (tid < CU && tid < ul) ? g_sc_u[bt * CU + tid] : -INFINITY;
    float um = blockReduceMax256(uv, red);
    float ue = (tid < CU && tid < ul) ? expf(uv - um) : 0.f;
    float us = blockReduceSum256(ue, red);
    if (tid < CU) su[tid] = ue / us;
    float wv[4], we[4];
    float wm = -INFINITY;
    #pragma unroll
    for (int i = 0; i < 4; i++) {
        int idx = tid + 256 * i;
        wv[i] = (idx < wl) ? g_sc_w[(size_t)bt * CW + idx] : -INFINITY;
        wm = fmaxf(wm, wv[i]);
    }
    wm = blockReduceMax256(wm, red);
    float wsum = 0.f;
    #pragma unroll
    for (int i = 0; i < 4; i++) {
        int idx = tid + 256 * i;
        we[i] = (idx < wl) ? expf(wv[i] - wm) : 0.f;
        wsum += we[i];
    }
    wsum = blockReduceSum256(wsum, red);
    #pragma unroll
    for (int i = 0; i < 4; i++) sw[tid + 256 * i] = we[i] / wsum;
    __syncthreads();
    if (tid < CU) {
        float v2 = (tid < ul) ? ss[seg[b * CU + tid]] * su[tid] : 0.f;
        su[tid] = v2;
    }
    __syncthreads();
    float pv[4];
    #pragma unroll
    for (int i = 0; i < 4; i++) {
        int idx = tid + 256 * i;
        pv[i] = (idx < wl) ? su[utt[b * CW + idx]] * sw[idx] : 0.f;
    }
    float pm = fmaxf(fmaxf(pv[0], pv[1]), fmaxf(pv[2], pv[3]));
    pm = blockReduceMax256(pm, red);
    float pe[4];
    float psum = 0.f;
    #pragma unroll
    for (int i = 0; i < 4; i++) { pe[i] = expf(pv[i] - pm); psum += pe[i]; }
    psum = blockReduceSum256(psum, red);
    #pragma unroll
    for (int i = 0; i < 4; i++)
        gb_suw[(size_t)bt * CW + tid + 256 * i] = __float2bfloat16(pe[i] / psum);
}

// ---------------- per-batch transpose of w_output -> bf16 [B,2M,W] ----------------
__global__ void transpose_w_kernel(const float* __restrict__ wo) {
    __shared__ float tile[32][33];
    int b = blockIdx.z;
    int w0 = blockIdx.x * 32, m0 = blockIdx.y * 32;
    int x = threadIdx.x, y = threadIdx.y;
    #pragma unroll
    for (int i = 0; i < 32; i += 8)
        tile[y + i][x] = wo[((size_t)b * CW + (w0 + y + i)) * CM2 + m0 + x];
    __syncthreads();
    #pragma unroll
    for (int i = 0; i < 32; i += 8)
        gb_wT[((size_t)b * CM2 + (m0 + y + i)) * CW + w0 + x] = __float2bfloat16(tile[x][y + i]);
}

// ---------------- in-place log_softmax: single-pass online max+sum ----------------
__global__ __launch_bounds__(256) void logsoftmax_kernel(float* __restrict__ out) {
    __shared__ float redm[8];
    __shared__ float reds[8];
    int row = blockIdx.x, tid = threadIdx.x;
    float* p = out + (size_t)row * CV;
    float m = -INFINITY, s = 0.f;
    for (int i = tid; i < CV; i += 256) {
        float v = p[i];
        if (v > m) { s *= expf(m - v); m = v; }
        s += expf(v - m);
    }
    #pragma unroll
    for (int o = 16; o; o >>= 1) {
        float om = __shfl_xor_sync(0xffffffffu, m, o);
        float os = __shfl_xor_sync(0xffffffffu, s, o);
        float M = fmaxf(m, om);
        s = s * expf(m - M) + os * expf(om - M);
        m = M;
    }
    if ((tid & 31) == 0) { redm[tid >> 5] = m; reds[tid >> 5] = s; }
    __syncthreads();
    if (tid < 32) {
        float mm = (tid < 8) ? redm[tid] : -INFINITY;
        float sv = (tid < 8) ? reds[tid] : 0.f;
        #pragma unroll
        for (int o = 4; o; o >>= 1) {
            float om = __shfl_xor_sync(0xffffffffu, mm, o);
            float os = __shfl_xor_sync(0xffffffffu, sv, o);
            float M = fmaxf(mm, om);
            float e1 = (sv > 0.f) ? sv * expf(mm - M) : 0.f;
            float e2 = (os > 0.f) ? os * expf(om - M) : 0.f;
            sv = e1 + e2;
            mm = M;
        }
        if (tid == 0) { redm[0] = mm; reds[0] = sv; }
    }
    __syncthreads();
    float lse = redm[0] + logf(reds[0]);
    for (int i = tid; i < CV; i += 256) p[i] -= lse;
}

// ---------------- launch ----------------
extern "C" void kernel_launch(void* const* d_in, const int* in_sizes, int n_in,
                              void* d_out, int out_size) {
    const int*   target   = (const int*)d_in[0];
    const float* embedding= (const float*)d_in[1];
    const float* W_ih0    = (const float*)d_in[2];
    const float* W_hh0    = (const float*)d_in[3];
    const float* b_ih0    = (const float*)d_in[4];
    const float* b_hh0    = (const float*)d_in[5];
    const float* W_ih1    = (const float*)d_in[6];
    const float* W_hh1    = (const float*)d_in[7];
    const float* b_ih1    = (const float*)d_in[8];
    const float* b_hh1    = (const float*)d_in[9];
    const float* att_s_w  = (const float*)d_in[10];
    const float* att_s_b  = (const float*)d_in[11];
    const float* att_u_w  = (const float*)d_in[12];
    const float* att_u_b  = (const float*)d_in[13];
    const float* att_w_w  = (const float*)d_in[14];
    const float* att_w_b  = (const float*)d_in[15];
    const float* out_w    = (const float*)d_in[16];
    const float* out_b    = (const float*)d_in[17];
    const float* s_output = (const float*)d_in[18];
    const float* u_output = (const float*)d_in[19];
    const float* w_output = (const float*)d_in[20];
    const int*   s_len    = (const int*)d_in[21];
    const int*   u_len    = (const int*)d_in[22];
    const int*   w_len    = (const int*)d_in[23];
    const int*   seg      = (const int*)d_in[24];
    const int*   utt      = (const int*)d_in[25];
    float* out = (float*)d_out;

    float *p_gi, *p_rnn, *p_ps, *p_pu, *p_scs, *p_scu, *p_scw;
    cudaGetSymbolAddress((void**)&p_gi, g_gi);
    cudaGetSymbolAddress((void**)&p_rnn, g_rnn);
    cudaGetSymbolAddress((void**)&p_ps, g_proj_s);
    cudaGetSymbolAddress((void**)&p_pu, g_proj_u);
    cudaGetSymbolAddress((void**)&p_scs, g_sc_s);
    cudaGetSymbolAddress((void**)&p_scu, g_sc_u);
    cudaGetSymbolAddress((void**)&p_scw, g_sc_w);
    __nv_bfloat16 *b_feat, *b_suw, *b_sout, *b_uout, *b_wout,
                  *b_wT, *b_pw, *b_Wih0, *b_atts, *b_attu, *b_attw, *b_outw, *b_emb;
    cudaGetSymbolAddress((void**)&b_emb, gb_emb);
    cudaGetSymbolAddress((void**)&b_feat, gb_feat);
    cudaGetSymbolAddress((void**)&b_suw, gb_suw);
    cudaGetSymbolAddress((void**)&b_sout, gb_sout);
    cudaGetSymbolAddress((void**)&b_uout, gb_uout);
    cudaGetSymbolAddress((void**)&b_wout, gb_wout);
    cudaGetSymbolAddress((void**)&b_wT, gb_wT);
    cudaGetSymbolAddress((void**)&b_pw, gb_pw);
    cudaGetSymbolAddress((void**)&b_Wih0, gb_Wih0);
    cudaGetSymbolAddress((void**)&b_atts, gb_atts);
    cudaGetSymbolAddress((void**)&b_attu, gb_attu);
    cudaGetSymbolAddress((void**)&b_attw, gb_attw);
    cudaGetSymbolAddress((void**)&b_outw, gb_outw);

    cudaFuncSetAttribute(mega_kernel,
                         cudaFuncAttributeMaxDynamicSharedMemorySize, GRU_SMEM);
    cudaFuncSetAttribute(bgemm_nt<true>,
                         cudaFuncAttributeMaxDynamicSharedMemorySize, BG_DYN);
    cudaFuncSetAttribute(bgemm_nt<false>,
                         cudaFuncAttributeMaxDynamicSharedMemorySize, BG_DYN);

    // 1. merged fp32->bf16 conversions (8 segments)
    convert_all_kernel<<<(unsigned)(SEG7 / 256), 256>>>(
        W_ih0, att_s_w, att_u_w, att_w_w, out_w, s_output, u_output, w_output);
    // 2. embedding gather
    embed_kernel<<<(CB * CT * CE + 255) / 256, 256>>>(target, embedding);
    // 3. gi0 = emb @ W_ih0^T + b_ih0
    bgemm_nt<false><<<dim3((CB * CT) / 128, C3H / 128, 1), 256, BG_DYN>>>(b_emb, b_Wih0, b_ih0, p_gi,
        CE, CE, CE, C3H, 0, 0, 0);
    // 4. MEGA: pipelined layer-0 + layer-1 GRU (inline gi1) + proj_w/atts/attu tiles
    mega_kernel<<<GNB0 + GNB1 + 512 + 8 + 64, 256, GRU_SMEM>>>(
        p_gi, W_hh0, b_hh0,
        W_ih1, W_hh1, b_ih1, b_hh1,
        p_rnn, b_feat,
        b_wout, b_attw, att_w_b, b_pw,
        b_sout, b_atts, att_s_b, p_ps,
        b_uout, b_attu, att_u_b, p_pu);
    // 5. raw scores
    attn_scores_kernel<<<(CB * CT * CS) / 8, 256>>>(p_rnn, p_ps, p_scs, CS);
    attn_scores_kernel<<<(CB * CT * CU) / 8, 256>>>(p_rnn, p_pu, p_scu, CU);
    bgemm_nt<false><<<dim3(CT / 128, CW / 128, CB), 256, BG_DYN>>>(b_feat + CM2, b_pw, nullptr, p_scw,
        CH, CF, CH, CW, (long)CT * CF, (long)CW * CH, (long)CT * CW);
    // 6. masked softmaxes + hierarchical combine + final softmax
    combine_kernel<<<CB * CT, 256>>>(s_len, u_len, w_len, seg, utt);
    // 7. context = suw @ w_output -> bf16 feat[:, :1024]
    transpose_w_kernel<<<dim3(CW / 32, CM2 / 32, CB), dim3(32, 8)>>>(w_output);
    bgemm_nt<true><<<dim3(CT / 128, CM2 / 128, CB), 256, BG_DYN>>>(b_suw, b_wT, nullptr, b_feat,
        CW, CW, CW, CF, (long)CT * CW, (long)CM2 * CW, (long)CT * CF);
    // 8. logits = feat @ out_w^T + out_b -> d_out (fp32)
    bgemm_nt<false><<<dim3((CB * CT) / 128, CV / 128, 1), 256, BG_DYN>>>(b_feat, b_outw, out_b, out,
        CF, CF, CF, CV, 0, 0, 0);
    // 9. in-place log_softmax (single-pass online)
    logsoftmax_kernel<<<CB * CT, 256>>>(out);
}

// round 17
// speedup vs baseline: 1.6367x; 1.1311x over previous
#include <cuda_runtime.h>
#include <cuda_bf16.h>
#include <math.h>

// ---------------- problem constants ----------------
#define CB 8       // batch
#define CT 128     // time
#define CE 512     // embed dim
#define CH 1024    // hidden
#define CM 512     // mem hidden
#define CM2 1024   // 2*M
#define CS 16
#define CU 128
#define CW 1024
#define CV 32000
#define C3H 3072
#define CF 2048    // H + 2M

// ---------------- fp32 scratch ----------------
__device__ float g_gi[CB * CT * C3H];
__device__ float g_rnn[CB * CT * CH];
__device__ float g_proj_s[CB * CS * CH];
__device__ float g_proj_u[CB * CU * CH];
__device__ float g_sc_s[CB * CT * CS];
__device__ float g_sc_u[CB * CT * CU];
__device__ float g_sc_w[CB * CT * CW];
__device__ unsigned g_bar_arr = 0;
__device__ unsigned g_bar_gen = 0;
__device__ unsigned g_bar1_arr = 0;
__device__ unsigned g_bar1_gen = 0;
__device__ unsigned g_prog0 = 0;

// ---------------- bf16 scratch ----------------
__device__ __nv_bfloat16 gb_emb[CB * CT * CE];
__device__ __nv_bfloat16 gb_feat[CB * CT * CF];
__device__ __nv_bfloat16 gb_suw[CB * CT * CW];
__device__ __nv_bfloat16 gb_sout[CB * CS * CM];
__device__ __nv_bfloat16 gb_uout[CB * CU * CM];
__device__ __nv_bfloat16 gb_wout[CB * CW * CM2];
__device__ __nv_bfloat16 gb_wT[CB * CM2 * CW];
__device__ __nv_bfloat16 gb_pw[CB * CW * CH];
__device__ __nv_bfloat16 gb_Wih0[C3H * CE];
__device__ __nv_bfloat16 gb_atts[CH * CM];
__device__ __nv_bfloat16 gb_attu[CH * CM];
__device__ __nv_bfloat16 gb_attw[CH * CM2];
__device__ __nv_bfloat16 gb_outw[(size_t)CV * CF];   // 131 MB
__device__ __nv_bfloat16 g_hbf1[2 * CB * CH];        // layer-1 h ring
__device__ __nv_bfloat16 g_h1s[(size_t)CT * CB * CH];// all layer-0 outputs [t][b][1024]

// ---------------- grid barrier (parametrized; R11-proven atomic-poll) ----------------
__device__ __forceinline__ void grid_sync_all(unsigned nb, unsigned* arr, unsigned* gen) {
    __threadfence();
    __syncthreads();
    if (threadIdx.x == 0) {
        unsigned g = atomicAdd(gen, 0u);
        if (atomicAdd(arr, 1u) == nb - 1u) {
            atomicExch(arr, 0u);
            __threadfence();
            atomicAdd(gen, 1u);
        } else {
            while (atomicAdd(gen, 0u) == g) { __nanosleep(32); }
        }
    }
    __syncthreads();
}

// ---------------- block reductions (256 threads) ----------------
__device__ __forceinline__ float blockReduceMax256(float v, float* red) {
    #pragma unroll
    for (int o = 16; o; o >>= 1) v = fmaxf(v, __shfl_xor_sync(0xffffffffu, v, o));
    if ((threadIdx.x & 31) == 0) red[threadIdx.x >> 5] = v;
    __syncthreads();
    if (threadIdx.x < 32) {
        float r = (threadIdx.x < 8) ? red[threadIdx.x] : -INFINITY;
        #pragma unroll
        for (int o = 4; o; o >>= 1) r = fmaxf(r, __shfl_xor_sync(0xffffffffu, r, o));
        if (threadIdx.x == 0) red[0] = r;
    }
    __syncthreads();
    float out = red[0];
    __syncthreads();
    return out;
}

__device__ __forceinline__ float blockReduceSum256(float v, float* red) {
    #pragma unroll
    for (int o = 16; o; o >>= 1) v += __shfl_xor_sync(0xffffffffu, v, o);
    if ((threadIdx.x & 31) == 0) red[threadIdx.x >> 5] = v;
    __syncthreads();
    if (threadIdx.x < 32) {
        float r = (threadIdx.x < 8) ? red[threadIdx.x] : 0.f;
        #pragma unroll
        for (int o = 4; o; o >>= 1) r += __shfl_xor_sync(0xffffffffu, r, o);
        if (threadIdx.x == 0) red[0] = r;
    }
    __syncthreads();
    float out = red[0];
    __syncthreads();
    return out;
}

// ---------------- single merged fp32->bf16 convert (8 segments) ----------------
#define SEG0 (C3H * CE / 4)
#define SEG1 (SEG0 + CH * CM / 4)
#define SEG2 (SEG1 + CH * CM / 4)
#define SEG3 (SEG2 + CH * CM2 / 4)
#define SEG4 (SEG3 + (size_t)CV * CF / 4)
#define SEG5 (SEG4 + CB * CS * CM / 4)
#define SEG6 (SEG5 + CB * CU * CM / 4)
#define SEG7 (SEG6 + CB * CW * CM2 / 4)

__global__ void convert_all_kernel(
    const float* __restrict__ s0, const float* __restrict__ s1,
    const float* __restrict__ s2, const float* __restrict__ s3,
    const float* __restrict__ s4, const float* __restrict__ s5,
    const float* __restrict__ s6, const float* __restrict__ s7)
{
    size_t i4 = (size_t)blockIdx.x * 256 + threadIdx.x;
    const float* src; __nv_bfloat16* dst; size_t off;
    if      (i4 < SEG0) { src = s0; dst = gb_Wih0; off = i4; }
    else if (i4 < SEG1) { src = s1; dst = gb_atts; off = i4 - SEG0; }
    else if (i4 < SEG2) { src = s2; dst = gb_attu; off = i4 - SEG1; }
    else if (i4 < SEG3) { src = s3; dst = gb_attw; off = i4 - SEG2; }
    else if (i4 < SEG4) { src = s4; dst = gb_outw; off = i4 - SEG3; }
    else if (i4 < SEG5) { src = s5; dst = gb_sout; off = i4 - SEG4; }
    else if (i4 < SEG6) { src = s6; dst = gb_uout; off = i4 - SEG5; }
    else if (i4 < SEG7) { src = s7; dst = gb_wout; off = i4 - SEG6; }
    else return;
    float4 v = ((const float4*)src)[off];
    __nv_bfloat162* d = (__nv_bfloat162*)(dst + off * 4);
    d[0] = __floats2bfloat162_rn(v.x, v.y);
    d[1] = __floats2bfloat162_rn(v.z, v.w);
}

// ---------------- embedding gather ----------------
__global__ void embed_kernel(const int* __restrict__ target, const float* __restrict__ emb) {
    int i = blockIdx.x * blockDim.x + threadIdx.x;
    if (i < CB * CT * CE) {
        int bt = i / CE, e = i - bt * CE;
        gb_emb[i] = __float2bfloat16(emb[(size_t)target[bt] * CE + e]);
    }
}

// ---------------- mma / ldmatrix / cp.async helpers ----------------
__device__ __forceinline__ void mma_bf16(float* d, const unsigned* a, const unsigned* b) {
    asm volatile(
        "mma.sync.aligned.m16n8k16.row.col.f32.bf16.bf16.f32 "
        "{%0,%1,%2,%3}, {%4,%5,%6,%7}, {%8,%9}, {%0,%1,%2,%3};"
        : "+f"(d[0]), "+f"(d[1]), "+f"(d[2]), "+f"(d[3])
        : "r"(a[0]), "r"(a[1]), "r"(a[2]), "r"(a[3]), "r"(b[0]), "r"(b[1]));
}

__device__ __forceinline__ void ldsm4(unsigned& r0, unsigned& r1, unsigned& r2, unsigned& r3,
                                      unsigned addr) {
    asm volatile("ldmatrix.sync.aligned.m8n8.x4.shared.b16 {%0,%1,%2,%3}, [%4];"
        : "=r"(r0), "=r"(r1), "=r"(r2), "=r"(r3) : "r"(addr));
}

__device__ __forceinline__ void ldsm2(unsigned& r0, unsigned& r1, unsigned addr) {
    asm volatile("ldmatrix.sync.aligned.m8n8.x2.shared.b16 {%0,%1}, [%2];"
        : "=r"(r0), "=r"(r1) : "r"(addr));
}

__device__ __forceinline__ void cpa16(unsigned dst, const void* src) {
    asm volatile("cp.async.ca.shared.global [%0], [%1], 16;" :: "r"(dst), "l"(src));
}

__device__ __forceinline__ unsigned smem_u32(const void* p) {
    unsigned a;
    asm("{ .reg .u64 t; cvta.to.shared.u64 t, %1; cvt.u32.u64 %0, t; }" : "=r"(a) : "l"(p));
    return a;
}

// ---------------- bf16 tensor-core NT GEMM tile (device function) ----------------
#define BG_DYN (3 * 32768)

__device__ __forceinline__ void bgemm_tile(
    const __nv_bfloat16* __restrict__ A, const __nv_bfloat16* __restrict__ Bm,
    const float* __restrict__ bias, void* __restrict__ Cv,
    int K, int lda, int ldb, int ldc, long sA, long sB, long sC,
    int bx, int by, int bz, bool obf16, unsigned baseS)
{
    const __nv_bfloat16* Ab = A + (size_t)bz * sA + (size_t)(bx * 128) * lda;
    const __nv_bfloat16* Bb = Bm + (size_t)bz * sB + (size_t)(by * 128) * ldb;
    int tid = threadIdx.x;
    int warp = tid >> 5, lane = tid & 31;
    int wm = (warp >> 2) * 64, wn = (warp & 3) * 32;
    int lr = lane >> 2, lq = lane & 3;

    int r0 = tid >> 3, g0 = tid & 7;
    unsigned woff0 = (unsigned)(r0 * 128 + ((g0 ^ (r0 & 7)) << 4));
    const __nv_bfloat16* srcA = Ab + (size_t)r0 * lda + g0 * 8;
    const __nv_bfloat16* srcB = Bb + (size_t)r0 * ldb + g0 * 8;

    int lt = lane >> 3, rr = lane & 7;
    int gAoff = lt >> 1;
    unsigned rowA128[4]; unsigned swzA[4];
    #pragma unroll
    for (int mi = 0; mi < 4; mi++) {
        int row = wm + mi * 16 + ((lt & 1) << 3) + rr;
        rowA128[mi] = row * 128;
        swzA[mi] = row & 7;
    }
    int gBoff = lt & 1;
    unsigned rowB128[2]; unsigned swzB[2];
    #pragma unroll
    for (int np = 0; np < 2; np++) {
        int row = wn + np * 16 + ((lt >> 1) << 3) + rr;
        rowB128[np] = row * 128;
        swzB[np] = row & 7;
    }

    float acc[4][4][4];
    #pragma unroll
    for (int mi = 0; mi < 4; mi++)
        #pragma unroll
        for (int ni = 0; ni < 4; ni++)
            #pragma unroll
            for (int r = 0; r < 4; r++) acc[mi][ni][r] = 0.f;

#define STAGE_LOAD(st, kt) do { \
        unsigned sb_ = baseS + (unsigned)(st) * 32768u; \
        _Pragma("unroll") \
        for (int i_ = 0; i_ < 4; i_++) { \
            unsigned o_ = woff0 + (unsigned)i_ * 4096u; \
            size_t ro_ = (size_t)(i_ * 32); \
            cpa16(sb_ + o_, srcA + ro_ * lda + (kt)); \
            cpa16(sb_ + 16384u + o_, srcB + ro_ * ldb + (kt)); \
        } \
        asm volatile("cp.async.commit_group;"); } while (0)

    int nt = K / 64;
    STAGE_LOAD(0, 0);
    STAGE_LOAD(1, 64);

    for (int it = 0; it < nt; it++) {
        if (it + 1 < nt) asm volatile("cp.async.wait_group 1;");
        else             asm volatile("cp.async.wait_group 0;");
        __syncthreads();
        if (it + 2 < nt) {
            int st = (it + 2) % 3, kt = (it + 2) * 64;
            STAGE_LOAD(st, kt);
        }

        unsigned stA = baseS + (unsigned)(it % 3) * 32768u;
        unsigned stB = stA + 16384u;
        #pragma unroll
        for (int ks = 0; ks < 4; ks++) {
            const int kg = ks * 2;
            unsigned a[4][4], b[4][2];
            #pragma unroll
            for (int mi = 0; mi < 4; mi++)
                ldsm4(a[mi][0], a[mi][1], a[mi][2], a[mi][3],
                      stA + rowA128[mi] + ((unsigned)((kg + gAoff) ^ swzA[mi]) << 4));
            #pragma unroll
            for (int np = 0; np < 2; np++)
                ldsm4(b[2 * np][0], b[2 * np][1], b[2 * np + 1][0], b[2 * np + 1][1],
                      stB + rowB128[np] + ((unsigned)((kg + gBoff) ^ swzB[np]) << 4));
            #pragma unroll
            for (int mi = 0; mi < 4; mi++)
                #pragma unroll
                for (int ni = 0; ni < 4; ni++)
                    mma_bf16(acc[mi][ni], a[mi], b[ni]);
        }
    }
#undef STAGE_LOAD

    int m0 = bx * 128, n0 = by * 128;
    #pragma unroll
    for (int mi = 0; mi < 4; mi++) {
        #pragma unroll
        for (int ni = 0; ni < 4; ni++) {
            int m = m0 + wm + mi * 16 + lr;
            int n = n0 + wn + ni * 8 + lq * 2;
            float b0 = bias ? bias[n] : 0.f;
            float b1 = bias ? bias[n + 1] : 0.f;
            float v00 = acc[mi][ni][0] + b0, v01 = acc[mi][ni][1] + b1;
            float v10 = acc[mi][ni][2] + b0, v11 = acc[mi][ni][3] + b1;
            if (obf16) {
                __nv_bfloat16* Cb = (__nv_bfloat16*)Cv + (size_t)bz * sC;
                *(__nv_bfloat162*)(Cb + (size_t)m * ldc + n) = __floats2bfloat162_rn(v00, v01);
                *(__nv_bfloat162*)(Cb + (size_t)(m + 8) * ldc + n) = __floats2bfloat162_rn(v10, v11);
            } else {
                float* Cb = (float*)Cv + (size_t)bz * sC;
                *(float2*)(Cb + (size_t)m * ldc + n) = make_float2(v00, v01);
                *(float2*)(Cb + (size_t)(m + 8) * ldc + n) = make_float2(v10, v11);
            }
        }
    }
}

template<bool OB>
__global__ __launch_bounds__(256, 2) void bgemm_nt(
    const __nv_bfloat16* __restrict__ A, const __nv_bfloat16* __restrict__ Bm,
    const float* __restrict__ bias, void* __restrict__ Cv,
    int K, int lda, int ldb, int ldc, long sA, long sB, long sC)
{
    extern __shared__ unsigned bsm_dyn[];
    bgemm_tile(A, Bm, bias, Cv, K, lda, ldb, ldc, sA, sB, sC,
               blockIdx.x, blockIdx.y, blockIdx.z, OB, smem_u32(bsm_dyn));
}

// ---------------- layer-0 GRU block body (32 blocks x 32 units) ----------------
#define GNB0 32
#define GNB1 64
#define GKP 1032
#define GRU0_SMEM (104 * GKP * 2 + 2 * 96 * 9 * 4)
#define MEGA_SMEM 232448   // = 227 KB opt-in max; layer-1 uses exactly this

__device__ __forceinline__ void gru0_body(
    int bid, __nv_bfloat16* dyn,
    const float* __restrict__ gi, const float* __restrict__ Wh,
    const float* __restrict__ bh)
{
    __nv_bfloat16* whs = dyn;                       // [96][GKP]
    __nv_bfloat16* hs  = dyn + 96 * GKP;            // [8][GKP]
    float* gates = (float*)(dyn + 104 * GKP);       // [96][9]
    float* gis   = gates + 96 * 9;                  // [96][9]
    int tid = threadIdx.x, warp = tid >> 5, lane = tid & 31;
    int j0 = bid * 32;

    for (int idx = tid; idx < 96 * CH; idx += 256) {
        int row = idx >> 10, k = idx & (CH - 1);
        int gate = row >> 5, u = row & 31;
        whs[row * GKP + k] = __float2bfloat16(Wh[(size_t)(gate * CH + j0 + u) * CH + k]);
    }
    for (int idx = tid; idx < CB * GKP; idx += 256) hs[idx] = __float2bfloat16(0.f);

    int j = tid & 31, b = tid >> 5;
    float bhr = bh[j0 + j], bhz = bh[CH + j0 + j], bhn = bh[2 * CH + j0 + j];
    float hprev = 0.f;

    unsigned whb = (unsigned)__cvta_generic_to_shared(whs);
    unsigned hsb = (unsigned)__cvta_generic_to_shared(hs);
    int lt = lane >> 3, rr = lane & 7;
    unsigned aAddr = whb + (unsigned)(((warp << 4) + ((lt & 1) << 3) + rr) * GKP
                                      + ((lt >> 1) << 3)) * 2u;
    int ln = lane & 15;
    unsigned bAddr = hsb + (unsigned)((ln & 7) * GKP + ((ln >> 3) << 3)) * 2u;
    __syncthreads();

    for (int t = 0; t < CT; t++) {
        if (warp < 6) {
            float acc[4][4];
            #pragma unroll
            for (int i = 0; i < 4; i++)
                #pragma unroll
                for (int r = 0; r < 4; r++) acc[i][r] = 0.f;
            #pragma unroll 8
            for (int ks = 0; ks < 64; ks++) {
                unsigned av[4], bv[2];
                ldsm4(av[0], av[1], av[2], av[3], aAddr + ks * 32u);
                ldsm2(bv[0], bv[1], bAddr + ks * 32u);
                mma_bf16(acc[ks & 3], av, bv);
            }
            float c0 = acc[0][0] + acc[1][0] + acc[2][0] + acc[3][0];
            float c1 = acc[0][1] + acc[1][1] + acc[2][1] + acc[3][1];
            float c2 = acc[0][2] + acc[1][2] + acc[2][2] + acc[3][2];
            float c3 = acc[0][3] + acc[1][3] + acc[2][3] + acc[3][3];
            int r_ = lane >> 2, q = lane & 3;
            int rowb = (warp << 4) + r_;
            gates[rowb * 9 + 2 * q]           = c0;
            gates[rowb * 9 + 2 * q + 1]       = c1;
            gates[(rowb + 8) * 9 + 2 * q]     = c2;
            gates[(rowb + 8) * 9 + 2 * q + 1] = c3;
        } else {
            for (int idx = tid - 192; idx < 768; idx += 64) {
                int g = idx >> 8, rem = idx & 255, jj = rem & 31, bb = rem >> 5;
                gis[(g * 32 + jj) * 9 + bb] =
                    gi[(size_t)(bb * CT + t) * C3H + g * CH + j0 + jj];
            }
        }
        __syncthreads();

        float rg = 1.f / (1.f + expf(-(gis[j * 9 + b] + gates[j * 9 + b] + bhr)));
        float zg = 1.f / (1.f + expf(-(gis[(32 + j) * 9 + b] + gates[(32 + j) * 9 + b] + bhz)));
        float ng = tanhf(gis[(64 + j) * 9 + b] + rg * (gates[(64 + j) * 9 + b] + bhn));
        float hn = (1.f - zg) * ng + zg * hprev;
        hprev = hn;
        g_h1s[(size_t)t * (CB * CH) + b * CH + j0 + j] = __float2bfloat16(hn);

        grid_sync_all(GNB0, &g_bar_arr, &g_bar_gen);
        if (bid == 0 && tid == 0) atomicAdd(&g_prog0, 1u);   // h1[t] published

        const __nv_bfloat16* hb = g_h1s + (size_t)t * (CB * CH);
        for (int idx = tid; idx < CB * CH / 8; idx += 256) {
            int bb = idx >> 7, kk = (idx & 127) << 3;
            *(uint4*)(hs + bb * GKP + kk) = *(const uint4*)(hb + bb * CH + kk);
        }
        __syncthreads();
    }
}

// ---------------- layer-1 GRU block body (64 blocks x 16 units, fused single-pass) -----
// Zero-pad swizzled smem (granule g ^= row&7; all row strides ≡ 0 mod 128B):
//   rzw [32][2048]  rows: 0-15 r-gate, 16-31 z-gate; cols 0-1023 Wih, 1024-2047 Whh
//   nih [16][1024], nhh [16][1024]
//   hb  [8][2048]   cols 0-1023 = h1[t], 1024-2047 = hl1[t-1]
//   gbuf float[6][16][8] at byte 229376. Total = 232448 B exactly.
#define L1_NIH 65536
#define L1_NHH 81920
#define L1_HB  98304

__device__ __forceinline__ void gru1_body(
    int bid1, __nv_bfloat16* dyn,
    const float* __restrict__ Wih, const float* __restrict__ Whh,
    const float* __restrict__ bih, const float* __restrict__ bhh,
    float* __restrict__ rnn_out, __nv_bfloat16* __restrict__ featb)
{
    __nv_bfloat16* rzw = dyn;
    __nv_bfloat16* nih = dyn + L1_NIH;
    __nv_bfloat16* nhh = dyn + L1_NHH;
    __nv_bfloat16* hb  = dyn + L1_HB;
    float* gbuf = (float*)((char*)dyn + 229376);
    int tid = threadIdx.x, warp = tid >> 5, lane = tid & 31;
    int j0 = bid1 * 16;

    // stage fused r/z weights (swizzled)
    for (int idx = tid; idx < 32 * 2048; idx += 256) {
        int row = idx >> 11, k = idx & 2047;
        int gate = row >> 4, uu = row & 15;
        float v = (k < 1024) ? Wih[(size_t)(gate * CH + j0 + uu) * CH + k]
                             : Whh[(size_t)(gate * CH + j0 + uu) * CH + (k - 1024)];
        int g = k >> 3, w = k & 7;
        rzw[row * 2048 + (((g ^ (row & 7)) << 3) | w)] = __float2bfloat16(v);
    }
    // stage n weights (swizzled)
    for (int idx = tid; idx < 16 * 1024; idx += 256) {
        int row = idx >> 10, k = idx & 1023;
        int g = k >> 3, w = k & 7;
        int off = row * 1024 + (((g ^ (row & 7)) << 3) | w);
        nih[off] = __float2bfloat16(Wih[(size_t)(2 * CH + j0 + row) * CH + k]);
        nhh[off] = __float2bfloat16(Whh[(size_t)(2 * CH + j0 + row) * CH + k]);
    }
    // cooperative zero of hl1 ring (both parities)
    for (int idx = tid + bid1 * 256; idx < 2 * CB * CH; idx += GNB1 * 256)
        g_hbf1[idx] = __float2bfloat16(0.f);

    int u = tid & 15, b = tid >> 4;   // valid for tid < 128
    float bihr = 0, bihz = 0, bihn = 0, bhhr = 0, bhhz = 0, bhhn = 0;
    if (tid < 128) {
        bihr = bih[j0 + u]; bihz = bih[CH + j0 + u]; bihn = bih[2 * CH + j0 + u];
        bhhr = bhh[j0 + u]; bhhz = bhh[CH + j0 + u]; bhhn = bhh[2 * CH + j0 + u];
    }
    float hprev = 0.f;

    // task geometry: warps 0-3 = rz (tile = w>>1, kh = w&1); warp 4 = nih; warp 5 = nhh
    unsigned base = (unsigned)__cvta_generic_to_shared(dyn);
    int lt = lane >> 3, rr = lane & 7;
    int ghalfA = lt >> 1;
    unsigned aRowByte; int aGBase, asw;
    {
        int aRow; unsigned bufByte; int strideB;
        if (warp < 4) {
            int tile = warp >> 1;
            aRow = tile * 16 + ((lt & 1) << 3) + rr;
            bufByte = base; strideB = 4096; aGBase = (warp & 1) * 128;
        } else {
            aRow = ((lt & 1) << 3) + rr;
            bufByte = base + ((warp == 4) ? L1_NIH : L1_NHH) * 2u;
            strideB = 2048; aGBase = 0;
        }
        aRowByte = bufByte + (unsigned)aRow * (unsigned)strideB;
        asw = aRow & 7;
    }
    int ln = lane & 15, bRow = ln & 7, ghalfB = ln >> 3;
    int bGBase = (warp < 4) ? ((warp & 1) * 128) : ((warp == 4) ? 0 : 128);
    unsigned bRowByte = base + (unsigned)L1_HB * 2u + (unsigned)bRow * 4096u;
    int bsw = bRow;

    grid_sync_all(GNB1, &g_bar1_arr, &g_bar1_gen);   // ring zero visible to all

    for (int t = 0; t < CT; t++) {
        if (tid == 0) {
            while (atomicAdd(&g_prog0, 0u) <= (unsigned)t) { __nanosleep(32); }
            __threadfence();
        }
        __syncthreads();
        // fused load: hb cols 0-1023 = h1[t], cols 1024-2047 = hl1[t-1]
        {
            const __nv_bfloat16* s1 = g_h1s + (size_t)t * (CB * CH);
            const __nv_bfloat16* s2 = g_hbf1 + ((t + 1) & 1) * (CB * CH);
            #pragma unroll
            for (int i = 0; i < 8; i++) {
                int idx = tid + 256 * i;
                int half = idx >> 10, rem = idx & 1023;
                int bb = rem >> 7, g = rem & 127;
                const __nv_bfloat16* src = half ? s2 : s1;
                uint4 v = *(const uint4*)(src + bb * CH + g * 8);
                int gg = (half << 7) | g;
                *(uint4*)(hb + bb * 2048 + ((gg ^ bb) << 3)) = v;
            }
        }
        __syncthreads();
        if (warp < 6) {
            float acc[4][4];
            #pragma unroll
            for (int i = 0; i < 4; i++)
                #pragma unroll
                for (int r2 = 0; r2 < 4; r2++) acc[i][r2] = 0.f;
            #pragma unroll 8
            for (int ks = 0; ks < 64; ks++) {
                int gA = aGBase + ks * 2 + ghalfA;
                int gB = bGBase + ks * 2 + ghalfB;
                unsigned av[4], bv[2];
                ldsm4(av[0], av[1], av[2], av[3], aRowByte + ((unsigned)(gA ^ asw) << 4));
                ldsm2(bv[0], bv[1], bRowByte + ((unsigned)(gB ^ bsw) << 4));
                mma_bf16(acc[ks & 3], av, bv);
            }
            float c0 = acc[0][0] + acc[1][0] + acc[2][0] + acc[3][0];
            float c1 = acc[0][1] + acc[1][1] + acc[2][1] + acc[3][1];
            float c2 = acc[0][2] + acc[1][2] + acc[2][2] + acc[3][2];
            float c3 = acc[0][3] + acc[1][3] + acc[2][3] + acc[3][3];
            float* gs = gbuf + warp * 128;
            int r_ = lane >> 2, q = lane & 3;
            gs[r_ * 8 + 2 * q]           = c0;
            gs[r_ * 8 + 2 * q + 1]       = c1;
            gs[(r_ + 8) * 8 + 2 * q]     = c2;
            gs[(r_ + 8) * 8 + 2 * q + 1] = c3;
        }
        __syncthreads();
        if (tid < 128) {
            int o = u * 8 + b;
            float rp  = gbuf[o]       + gbuf[128 + o] + bihr + bhhr;
            float zp  = gbuf[256 + o] + gbuf[384 + o] + bihz + bhhz;
            float inn = gbuf[512 + o] + bihn;
            float hnn = gbuf[640 + o] + bhhn;
            float rg = 1.f / (1.f + expf(-rp));
            float zg = 1.f / (1.f + expf(-zp));
            float ng = tanhf(inn + rg * hnn);
            float hn = (1.f - zg) * ng + zg * hprev;
            hprev = hn;
            g_hbf1[(t & 1) * (CB * CH) + b * CH + j0 + u] = __float2bfloat16(hn);
            rnn_out[(size_t)(b * CT + t) * CH + j0 + u] = hn;
            featb[(size_t)(b * CT + t) * CF + CM2 + j0 + u] = __float2bfloat16(hn);
        }
        grid_sync_all(GNB1, &g_bar1_arr, &g_bar1_gen);
    }
    grid_sync_all(GNB1, &g_bar1_arr, &g_bar1_gen);
    if (bid1 == 0 && tid == 0) atomicExch(&g_prog0, 0u);     // replay-safe reset
}

// ---------------- mega kernel: pipelined 2-layer GRU + attn projections --------------
__global__ __launch_bounds__(256) void mega_kernel(
    const float* __restrict__ gi, const float* __restrict__ Wh0, const float* __restrict__ bh0,
    const float* __restrict__ Wih1, const float* __restrict__ Whh1,
    const float* __restrict__ bih1, const float* __restrict__ bhh1,
    float* __restrict__ rnn_out, __nv_bfloat16* __restrict__ featb,
    const __nv_bfloat16* __restrict__ wout, const __nv_bfloat16* __restrict__ attw,
    const float* __restrict__ attw_b, __nv_bfloat16* __restrict__ pw,
    const __nv_bfloat16* __restrict__ sout, const __nv_bfloat16* __restrict__ atts,
    const float* __restrict__ atts_b, float* __restrict__ ps,
    const __nv_bfloat16* __restrict__ uout, const __nv_bfloat16* __restrict__ attu,
    const float* __restrict__ attu_b, float* __restrict__ pu)
{
    extern __shared__ __nv_bfloat16 dyn[];
    int bid = blockIdx.x;
    if (bid < GNB0) {
        gru0_body(bid, dyn, gi, Wh0, bh0);
    } else if (bid < GNB0 + GNB1) {
        gru1_body(bid - GNB0, dyn, Wih1, Whh1, bih1, bhh1, rnn_out, featb);
    } else if (bid < GNB0 + GNB1 + 512) {
        int l = bid - GNB0 - GNB1;
        bgemm_tile(wout, attw, attw_b, pw, CM2, CM2, CM2, CH, 0, 0, 0,
                   l & 63, l >> 6, 0, true, smem_u32(dyn));
    } else if (bid < GNB0 + GNB1 + 520) {
        int l = bid - GNB0 - GNB1 - 512;
        bgemm_tile(sout, atts, atts_b, ps, CM, CM, CM, CH, 0, 0, 0,
                   0, l, 0, false, smem_u32(dyn));
    } else {
        int l = bid - GNB0 - GNB1 - 520;
        bgemm_tile(uout, attu, attu_b, pu, CM, CM, CM, CH, 0, 0, 0,
                   l & 7, l >> 3, 0, false, smem_u32(dyn));
    }
}

// ---------------- small attention scores (one warp per dot) ----------------
__global__ void attn_scores_kernel(const float* __restrict__ q, const float* __restrict__ proj,
                                   float* __restrict__ out, int N) {
    int gw = (blockIdx.x * blockDim.x + threadIdx.x) >> 5;
    int lane = threadIdx.x & 31;
    if (gw >= CB * CT * N) return;
    int n = gw % N;
    int bt = gw / N;
    int b = bt / CT;
    const float* qp = q + (size_t)bt * CH;
    const float* pp = proj + (size_t)(b * N + n) * CH;
    float acc = 0.f;
    for (int k = lane * 4; k < CH; k += 128) {
        float4 qa = *(const float4*)(qp + k);
        float4 pa = *(const float4*)(pp + k);
        acc += qa.x * pa.x + qa.y * pa.y + qa.z * pa.z + qa.w * pa.w;
    }
    #pragma unroll
    for (int o = 16; o; o >>= 1) acc += __shfl_xor_sync(0xffffffffu, acc, o);
    if (lane == 0) out[gw] = acc;
}

// ---------------- fused masked softmaxes + hierarchical combine (bf16 out) ----------------
__global__ __launch_bounds__(256) void combine_kernel(
    const int* __restrict__ s_len, const int* __restrict__ u_len, const int* __restrict__ w_len,
    const int* __restrict__ seg, const int* __restrict__ utt)
{
    int bt = blockIdx.x, b = bt / CT, tid = threadIdx.x;
    __shared__ float ss[CS];
    __shared__ float su[CU];
    __shared__ float sw[CW];
    __shared__ float red[32];
    int sl = s_len[b], ul = u_len[b], wl = w_len[b];

    if (tid < 32) {
        float v = (tid < sl) ? g_sc_s[bt * CS + tid] : -INFINITY;
        float m = v;
        #pragma unroll
        for (int o = 16; o; o >>= 1) m = fmaxf(m, __shfl_xor_sync(0xffffffffu, m, o));
        float e = (tid < sl) ? expf(v - m) : 0.f;
        float s = e;
        #pragma unroll
        for (int o = 16; o; o >>= 1) s += __shfl_xor_sync(0xffffffffu, s, o);
        if (tid < CS) ss[tid] = e / s;
    }
    float uv = (tid < CU && tid < ul) ? g_sc_u[bt * CU + tid] : -INFINITY;
    float um = blockReduceMax256(uv, red);
    float ue = (tid < CU && tid < ul) ? expf(uv - um) : 0.f;
    float us = blockReduceSum256(ue, red);
    if (tid < CU) su[tid] = ue / us;
    float wv[4], we[4];
    float wm = -INFINITY;
    #pragma unroll
    for (int i = 0; i < 4; i++) {
        int idx = tid + 256 * i;
        wv[i] = (idx < wl) ? g_sc_w[(size_t)bt * CW + idx] : -INFINITY;
        wm = fmaxf(wm, wv[i]);
    }
    wm = blockReduceMax256(wm, red);
    float wsum = 0.f;
    #pragma unroll
    for (int i = 0; i < 4; i++) {
        int idx = tid + 256 * i;
        we[i] = (idx < wl) ? expf(wv[i] - wm) : 0.f;
        wsum += we[i];
    }
    wsum = blockReduceSum256(wsum, red);
    #pragma unroll
    for (int i = 0; i < 4; i++) sw[tid + 256 * i] = we[i] / wsum;
    __syncthreads();
    if (tid < CU) {
        float v2 = (tid < ul) ? ss[seg[b * CU + tid]] * su[tid] : 0.f;
        su[tid] = v2;
    }
    __syncthreads();
    float pv[4];
    #pragma unroll
    for (int i = 0; i < 4; i++) {
        int idx = tid + 256 * i;
        pv[i] = (idx < wl) ? su[utt[b * CW + idx]] * sw[idx] : 0.f;
    }
    float pm = fmaxf(fmaxf(pv[0], pv[1]), fmaxf(pv[2], pv[3]));
    pm = blockReduceMax256(pm, red);
    float pe[4];
    float psum = 0.f;
    #pragma unroll
    for (int i = 0; i < 4; i++) { pe[i] = expf(pv[i] - pm); psum += pe[i]; }
    psum = blockReduceSum256(psum, red);
    #pragma unroll
    for (int i = 0; i < 4; i++)
        gb_suw[(size_t)bt * CW + tid + 256 * i] = __float2bfloat16(pe[i] / psum);
}

// ---------------- per-batch transpose of w_output -> bf16 [B,2M,W] ----------------
__global__ void transpose_w_kernel(const float* __restrict__ wo) {
    __shared__ float tile[32][33];
    int b = blockIdx.z;
    int w0 = blockIdx.x * 32, m0 = blockIdx.y * 32;
    int x = threadIdx.x, y = threadIdx.y;
    #pragma unroll
    for (int i = 0; i < 32; i += 8)
        tile[y + i][x] = wo[((size_t)b * CW + (w0 + y + i)) * CM2 + m0 + x];
    __syncthreads();
    #pragma unroll
    for (int i = 0; i < 32; i += 8)
        gb_wT[((size_t)b * CM2 + (m0 + y + i)) * CW + w0 + x] = __float2bfloat16(tile[x][y + i]);
}

// ---------------- in-place log_softmax: single-pass online max+sum ----------------
__global__ __launch_bounds__(256) void logsoftmax_kernel(float* __restrict__ out) {
    __shared__ float redm[8];
    __shared__ float reds[8];
    int row = blockIdx.x, tid = threadIdx.x;
    float* p = out + (size_t)row * CV;
    float m = -INFINITY, s = 0.f;
    for (int i = tid; i < CV; i += 256) {
        float v = p[i];
        if (v > m) { s *= expf(m - v); m = v; }
        s += expf(v - m);
    }
    #pragma unroll
    for (int o = 16; o; o >>= 1) {
        float om = __shfl_xor_sync(0xffffffffu, m, o);
        float os = __shfl_xor_sync(0xffffffffu, s, o);
        float M = fmaxf(m, om);
        s = s * expf(m - M) + os * expf(om - M);
        m = M;
    }
    if ((tid & 31) == 0) { redm[tid >> 5] = m; reds[tid >> 5] = s; }
    __syncthreads();
    if (tid < 32) {
        float mm = (tid < 8) ? redm[tid] : -INFINITY;
        float sv = (tid < 8) ? reds[tid] : 0.f;
        #pragma unroll
        for (int o = 4; o; o >>= 1) {
            float om = __shfl_xor_sync(0xffffffffu, mm, o);
            float os = __shfl_xor_sync(0xffffffffu, sv, o);
            float M = fmaxf(mm, om);
            float e1 = (sv > 0.f) ? sv * expf(mm - M) : 0.f;
            float e2 = (os > 0.f) ? os * expf(om - M) : 0.f;
            sv = e1 + e2;
            mm = M;
        }
        if (tid == 0) { redm[0] = mm; reds[0] = sv; }
    }
    __syncthreads();
    float lse = redm[0] + logf(reds[0]);
    for (int i = tid; i < CV; i += 256) p[i] -= lse;
}

// ---------------- launch ----------------
extern "C" void kernel_launch(void* const* d_in, const int* in_sizes, int n_in,
                              void* d_out, int out_size) {
    const int*   target   = (const int*)d_in[0];
    const float* embedding= (const float*)d_in[1];
    const float* W_ih0    = (const float*)d_in[2];
    const float* W_hh0    = (const float*)d_in[3];
    const float* b_ih0    = (const float*)d_in[4];
    const float* b_hh0    = (const float*)d_in[5];
    const float* W_ih1    = (const float*)d_in[6];
    const float* W_hh1    = (const float*)d_in[7];
    const float* b_ih1    = (const float*)d_in[8];
    const float* b_hh1    = (const float*)d_in[9];
    const float* att_s_w  = (const float*)d_in[10];
    const float* att_s_b  = (const float*)d_in[11];
    const float* att_u_w  = (const float*)d_in[12];
    const float* att_u_b  = (const float*)d_in[13];
    const float* att_w_w  = (const float*)d_in[14];
    const float* att_w_b  = (const float*)d_in[15];
    const float* out_w    = (const float*)d_in[16];
    const float* out_b    = (const float*)d_in[17];
    const float* s_output = (const float*)d_in[18];
    const float* u_output = (const float*)d_in[19];
    const float* w_output = (const float*)d_in[20];
    const int*   s_len    = (const int*)d_in[21];
    const int*   u_len    = (const int*)d_in[22];
    const int*   w_len    = (const int*)d_in[23];
    const int*   seg      = (const int*)d_in[24];
    const int*   utt      = (const int*)d_in[25];
    float* out = (float*)d_out;

    float *p_gi, *p_rnn, *p_ps, *p_pu, *p_scs, *p_scu, *p_scw;
    cudaGetSymbolAddress((void**)&p_gi, g_gi);
    cudaGetSymbolAddress((void**)&p_rnn, g_rnn);
    cudaGetSymbolAddress((void**)&p_ps, g_proj_s);
    cudaGetSymbolAddress((void**)&p_pu, g_proj_u);
    cudaGetSymbolAddress((void**)&p_scs, g_sc_s);
    cudaGetSymbolAddress((void**)&p_scu, g_sc_u);
    cudaGetSymbolAddress((void**)&p_scw, g_sc_w);
    __nv_bfloat16 *b_feat, *b_suw, *b_sout, *b_uout, *b_wout,
                  *b_wT, *b_pw, *b_Wih0, *b_atts, *b_attu, *b_attw, *b_outw, *b_emb;
    cudaGetSymbolAddress((void**)&b_emb, gb_emb);
    cudaGetSymbolAddress((void**)&b_feat, gb_feat);
    cudaGetSymbolAddress((void**)&b_suw, gb_suw);
    cudaGetSymbolAddress((void**)&b_sout, gb_sout);
    cudaGetSymbolAddress((void**)&b_uout, gb_uout);
    cudaGetSymbolAddress((void**)&b_wout, gb_wout);
    cudaGetSymbolAddress((void**)&b_wT, gb_wT);
    cudaGetSymbolAddress((void**)&b_pw, gb_pw);
    cudaGetSymbolAddress((void**)&b_Wih0, gb_Wih0);
    cudaGetSymbolAddress((void**)&b_atts, gb_atts);
    cudaGetSymbolAddress((void**)&b_attu, gb_attu);
    cudaGetSymbolAddress((void**)&b_attw, gb_attw);
    cudaGetSymbolAddress((void**)&b_outw, gb_outw);

    cudaFuncSetAttribute(mega_kernel,
                         cudaFuncAttributeMaxDynamicSharedMemorySize, MEGA_SMEM);
    cudaFuncSetAttribute(bgemm_nt<true>,
                         cudaFuncAttributeMaxDynamicSharedMemorySize, BG_DYN);
    cudaFuncSetAttribute(bgemm_nt<false>,
                         cudaFuncAttributeMaxDynamicSharedMemorySize, BG_DYN);

    // 1. merged fp32->bf16 conversions (8 segments)
    convert_all_kernel<<<(unsigned)(SEG7 / 256), 256>>>(
        W_ih0, att_s_w, att_u_w, att_w_w, out_w, s_output, u_output, w_output);
    // 2. embedding gather
    embed_kernel<<<(CB * CT * CE + 255) / 256, 256>>>(target, embedding);
    // 3. gi0 = emb @ W_ih0^T + b_ih0
    bgemm_nt<false><<<dim3((CB * CT) / 128, C3H / 128, 1), 256, BG_DYN>>>(b_emb, b_Wih0, b_ih0, p_gi,
        CE, CE, CE, C3H, 0, 0, 0);
    // 4. MEGA: pipelined layer-0 + fused single-pass layer-1 + proj_w/atts/attu tiles
    mega_kernel<<<GNB0 + GNB1 + 512 + 8 + 64, 256, MEGA_SMEM>>>(
        p_gi, W_hh0, b_hh0,
        W_ih1, W_hh1, b_ih1, b_hh1,
        p_rnn, b_feat,
        b_wout, b_attw, att_w_b, b_pw,
        b_sout, b_atts, att_s_b, p_ps,
        b_uout, b_attu, att_u_b, p_pu);
    // 5. raw scores
    attn_scores_kernel<<<(CB * CT * CS) / 8, 256>>>(p_rnn, p_ps, p_scs, CS);
    attn_scores_kernel<<<(CB * CT * CU) / 8, 256>>>(p_rnn, p_pu, p_scu, CU);
    bgemm_nt<false><<<dim3(CT / 128, CW / 128, CB), 256, BG_DYN>>>(b_feat + CM2, b_pw, nullptr, p_scw,
        CH, CF, CH, CW, (long)CT * CF, (long)CW * CH, (long)CT * CW);
    // 6. masked softmaxes + hierarchical combine + final softmax
    combine_kernel<<<CB * CT, 256>>>(s_len, u_len, w_len, seg, utt);
    // 7. context = suw @ w_output -> bf16 feat[:, :1024]
    transpose_w_kernel<<<dim3(CW / 32, CM2 / 32, CB), dim3(32, 8)>>>(w_output);
    bgemm_nt<true><<<dim3(CT / 128, CM2 / 128, CB), 256, BG_DYN>>>(b_suw, b_wT, nullptr, b_feat,
        CW, CW, CW, CF, (long)CT * CW, (long)CM2 * CW, (long)CT * CF);
    // 8. logits = feat @ out_w^T + out_b -> d_out (fp32)
    bgemm_nt<false><<<dim3((CB * CT) / 128, CV / 128, 1), 256, BG_DYN>>>(b_feat, b_outw, out_b, out,
        CF, CF, CF, CV, 0, 0, 0);
    // 9. in-place log_softmax (single-pass online)
    logsoftmax_kernel<<<CB * CT, 256>>>(out);
}